// round 6
// baseline (speedup 1.0000x reference)
#include <cuda_runtime.h>
#include <cuda_bf16.h>
#include <cstdint>

// Problem constants
#define BB 8
#define SS 64
#define NN 256
#define FF 16
#define HH 16
#define CC 4096            // N*H  (= GEMM M)
#define COLS 512           // B*S  (= GEMM Ncol)
#define KTOT 12288         // C*3  (= GEMM K)
#define ALPHA 0.2f
#define EPS 1e-5f

// GEMM tiling (IMMA int8 path)
#define BK 128                      // int8 K elements per stage (128B rows)
#define TILEB 16384                 // 128 rows x 128 B, xor-swizzled
#define STAGEB 65536                // a1, a0, b1, b0 tiles
#define NSTAGE 3
#define NIT (KTOT / BK)             // 96
#define SMEM_DYN (NSTAGE * STAGEB)  // 196608

// ---------------- device scratch (no allocations allowed) -------------------
__device__ float    g_Wh[COLS * NN * HH];
__device__ float    g_f1[COLS * NN];
__device__ float    g_f2[COLS * NN];
__device__ unsigned g_mask[NN * 8];
__device__ float    g_S[(size_t)COLS * CC];        // spatial [col][c]
__device__ float    g_Smax[COLS];
__device__ int8_t   g_A1[(size_t)CC * KTOT];       // 50 MB
__device__ int8_t   g_A0[(size_t)CC * KTOT];       // 50 MB
__device__ int8_t   g_B1[(size_t)COLS * KTOT];
__device__ int8_t   g_B0[(size_t)COLS * KTOT];
__device__ float    g_sA[CC];
__device__ float    g_sB[COLS];
__device__ float    g_Yt[(size_t)COLS * CC];       // conv out [col][o]

// ---------------- PTX helpers ----------------------------------------------
__device__ __forceinline__ void cp16(unsigned dst, const void* src) {
    asm volatile("cp.async.cg.shared.global [%0], [%1], 16;" :: "r"(dst), "l"(src) : "memory");
}
__device__ __forceinline__ void cp_commit() {
    asm volatile("cp.async.commit_group;" ::: "memory");
}
__device__ __forceinline__ void ldsm4(unsigned* r, unsigned addr) {
    asm volatile("ldmatrix.sync.aligned.m8n8.x4.shared.b16 {%0,%1,%2,%3}, [%4];"
                 : "=r"(r[0]), "=r"(r[1]), "=r"(r[2]), "=r"(r[3]) : "r"(addr));
}
__device__ __forceinline__ void imma16832(int* d, const unsigned* a, const unsigned* b) {
    asm volatile(
        "mma.sync.aligned.m16n8k32.row.col.s32.s8.s8.s32 "
        "{%0,%1,%2,%3}, {%4,%5,%6,%7}, {%8,%9}, {%0,%1,%2,%3};"
        : "+r"(d[0]), "+r"(d[1]), "+r"(d[2]), "+r"(d[3])
        : "r"(a[0]), "r"(a[1]), "r"(a[2]), "r"(a[3]), "r"(b[0]), "r"(b[1]));
}
__device__ __forceinline__ void split15(float v, float inv, int8_t& hi, int8_t& lo) {
    int a = __float2int_rn(v * inv);            // in [-16383, 16383]
    int h = (a + 64) >> 7;
    if (h > 127) h = 127;
    int l = a - (h << 7);
    hi = (int8_t)h;
    lo = (int8_t)l;
}

// ---------------------------------------------------------------------------
// Kernel 0: adjacency bitmask
// ---------------------------------------------------------------------------
__global__ void k_mask(const float* __restrict__ adj) {
    int idx = blockIdx.x * blockDim.x + threadIdx.x;
    if (idx >= NN * 8) return;
    int i = idx >> 3, w = idx & 7;
    unsigned m = 0;
#pragma unroll
    for (int b = 0; b < 32; b++)
        if (adj[i * NN + w * 32 + b] > 0.0f) m |= (1u << b);
    g_mask[idx] = m;
}

// ---------------------------------------------------------------------------
// Kernel 1: Wh = x @ W ; f1 = Wh.a1 ; f2 = Wh.a2
// ---------------------------------------------------------------------------
__global__ void k_wh(const float* __restrict__ x, const float* __restrict__ W,
                     const float* __restrict__ a1, const float* __restrict__ a2) {
    __shared__ float sW[FF * HH];
    __shared__ float sa1[HH], sa2[HH];
    int t = threadIdx.x;
    sW[t] = W[t];
    if (t < HH) { sa1[t] = a1[t]; sa2[t] = a2[t]; }
    __syncthreads();

    int bs = blockIdx.x;
    const float* xr = x + (size_t)(bs * NN + t) * FF;
    float xv[FF];
#pragma unroll
    for (int f = 0; f < FF; f += 4) {
        float4 v = *(const float4*)(xr + f);
        xv[f] = v.x; xv[f + 1] = v.y; xv[f + 2] = v.z; xv[f + 3] = v.w;
    }
    float wh[HH];
#pragma unroll
    for (int h = 0; h < HH; h++) wh[h] = 0.0f;
#pragma unroll
    for (int f = 0; f < FF; f++)
#pragma unroll
        for (int h = 0; h < HH; h++) wh[h] += xv[f] * sW[f * HH + h];

    float f1 = 0.0f, f2 = 0.0f;
#pragma unroll
    for (int h = 0; h < HH; h++) { f1 += wh[h] * sa1[h]; f2 += wh[h] * sa2[h]; }

    float* whr = g_Wh + (size_t)(bs * NN + t) * HH;
#pragma unroll
    for (int h = 0; h < HH; h += 4)
        *(float4*)(whr + h) = make_float4(wh[h], wh[h + 1], wh[h + 2], wh[h + 3]);
    g_f1[bs * NN + t] = f1;
    g_f2[bs * NN + t] = f2;
}

// ---------------------------------------------------------------------------
// Kernel 2: attention softmax + spatial -> g_S[col][c]; also block max -> g_Smax
// ---------------------------------------------------------------------------
__global__ void k_attn() {
    __shared__ float    sWh[NN * HH];
    __shared__ float    sf2[NN];
    __shared__ unsigned smask[NN * 8];
    __shared__ float    sred[256];

    int bs = blockIdx.x;
    int t = threadIdx.x;

    for (int idx = t; idx < NN * HH; idx += 256) sWh[idx] = g_Wh[(size_t)bs * NN * HH + idx];
    sf2[t] = g_f2[bs * NN + t];
    for (int idx = t; idx < NN * 8; idx += 256) smask[idx] = g_mask[idx];
    __syncthreads();

    float f1i = g_f1[bs * NN + t];

    float m = -1e30f;
#pragma unroll 1
    for (int jw = 0; jw < 8; jw++) {
        unsigned wd = smask[t * 8 + jw];
#pragma unroll
        for (int bit = 0; bit < 32; bit++) {
            float e = f1i + sf2[jw * 32 + bit];
            e = e > 0.0f ? e : ALPHA * e;
            if ((wd >> bit) & 1u) m = fmaxf(m, e);
        }
    }

    float sum = 0.0f;
    float acc[HH];
#pragma unroll
    for (int h = 0; h < HH; h++) acc[h] = 0.0f;

#pragma unroll 1
    for (int jw = 0; jw < 8; jw++) {
        unsigned wd = smask[t * 8 + jw];
#pragma unroll
        for (int bit = 0; bit < 32; bit++) {
            int j = jw * 32 + bit;
            float e = f1i + sf2[j];
            e = e > 0.0f ? e : ALPHA * e;
            float w = ((wd >> bit) & 1u) ? __expf(e - m) : 0.0f;
            sum += w;
#pragma unroll
            for (int h = 0; h < HH; h++) acc[h] += w * sWh[j * HH + h];
        }
    }

    float inv = 1.0f / sum;
    float lmax = 0.0f;
    float* so = g_S + (size_t)bs * CC + t * HH;
#pragma unroll
    for (int h = 0; h < HH; h += 4) {
        float4 v = make_float4(acc[h] * inv, acc[h + 1] * inv,
                               acc[h + 2] * inv, acc[h + 3] * inv);
        *(float4*)(so + h) = v;
        lmax = fmaxf(lmax, fmaxf(fmaxf(fabsf(v.x), fabsf(v.y)),
                                 fmaxf(fabsf(v.z), fabsf(v.w))));
    }

    sred[t] = lmax;
    __syncthreads();
#pragma unroll
    for (int s = 128; s > 0; s >>= 1) {
        if (t < s) sred[t] = fmaxf(sred[t], sred[t + s]);
        __syncthreads();
    }
    if (t == 0) g_Smax[bs] = sred[0];
}

// ---------------------------------------------------------------------------
// Kernel 3a: quantize conv weights: per-row 15-bit -> (a1, a0) int8 limbs
// ---------------------------------------------------------------------------
__global__ void k_quantA(const float* __restrict__ w) {
    __shared__ float red[256];
    int row = blockIdx.x;
    int t = threadIdx.x;
    const float* src = w + (size_t)row * KTOT;

    float lm = 0.0f;
#pragma unroll 1
    for (int k = t * 4; k < KTOT; k += 1024) {
        float4 v = *(const float4*)(src + k);
        lm = fmaxf(lm, fmaxf(fmaxf(fabsf(v.x), fabsf(v.y)),
                             fmaxf(fabsf(v.z), fabsf(v.w))));
    }
    red[t] = lm;
    __syncthreads();
#pragma unroll
    for (int s = 128; s > 0; s >>= 1) {
        if (t < s) red[t] = fmaxf(red[t], red[t + s]);
        __syncthreads();
    }
    float mx = red[0];
    float sA = mx > 0.0f ? mx / 16383.0f : 1.0f;
    float inv = mx > 0.0f ? 16383.0f / mx : 0.0f;
    if (t == 0) g_sA[row] = sA;

#pragma unroll 1
    for (int k = t * 4; k < KTOT; k += 1024) {
        float4 v = *(const float4*)(src + k);
        float vv[4] = {v.x, v.y, v.z, v.w};
        int8_t h[4], l[4];
#pragma unroll
        for (int q = 0; q < 4; q++) split15(vv[q], inv, h[q], l[q]);
        *(uint32_t*)(g_A1 + (size_t)row * KTOT + k) = *(uint32_t*)h;
        *(uint32_t*)(g_A0 + (size_t)row * KTOT + k) = *(uint32_t*)l;
    }
}

// ---------------------------------------------------------------------------
// Kernel 3b: build + quantize B (K-major, [col][c*3+tap]) from g_S
// ---------------------------------------------------------------------------
__global__ void k_buildB() {
    int col = blockIdx.x;           // 0..511
    int s = col & 63;
    float m = g_Smax[col];
    if (s > 0)  m = fmaxf(m, g_Smax[col - 1]);
    if (s < 63) m = fmaxf(m, g_Smax[col + 1]);
    float sB = m > 0.0f ? m / 16383.0f : 1.0f;
    float inv = m > 0.0f ? 16383.0f / m : 0.0f;
    if (threadIdx.x == 0) g_sB[col] = sB;

    for (int c = threadIdx.x; c < CC; c += 256) {
        float vm = (s > 0)  ? g_S[(size_t)(col - 1) * CC + c] : 0.0f;
        float v0 =            g_S[(size_t)col * CC + c];
        float vp = (s < 63) ? g_S[(size_t)(col + 1) * CC + c] : 0.0f;
        float t3[3] = {vm, v0, vp};
        size_t base = (size_t)col * KTOT + 3 * (size_t)c;
#pragma unroll
        for (int tap = 0; tap < 3; tap++) {
            int8_t h, l;
            split15(t3[tap], inv, h, l);
            g_B1[base + tap] = h;
            g_B0[base + tap] = l;
        }
    }
}

// ---------------------------------------------------------------------------
// Kernel 4: IMMA int8 2-limb GEMM. D = sA*sB*(a1b1*2^14 + (a1b0+a0b1)*2^7)
// 128x128 CTA tile, BK=128 int8, 3 stages, 8 warps (4M x 2N), warp m32n64.
// ---------------------------------------------------------------------------
__device__ __forceinline__ void issue_stage(unsigned sbs, int kb, int t) {
    int row = t >> 1;                   // 0..127 (A row / B col within tile)
    int h2 = t & 1;
    unsigned rowB = (unsigned)(row * 128);
    unsigned swz = (unsigned)((row & 7) << 4);
    const int8_t* a1 = g_A1 + ((size_t)(blockIdx.y * 128 + row)) * KTOT + kb;
    const int8_t* a0 = g_A0 + ((size_t)(blockIdx.y * 128 + row)) * KTOT + kb;
    const int8_t* b1 = g_B1 + ((size_t)(blockIdx.x * 128 + row)) * KTOT + kb;
    const int8_t* b0 = g_B0 + ((size_t)(blockIdx.x * 128 + row)) * KTOT + kb;
#pragma unroll
    for (int j = 0; j < 4; j++) {
        int cidx = j * 2 + h2;          // 0..7 16B chunks
        unsigned dsw = rowB + (((unsigned)(cidx * 16)) ^ swz);
        cp16(sbs + dsw,          a1 + cidx * 16);
        cp16(sbs + 16384 + dsw,  a0 + cidx * 16);
        cp16(sbs + 32768 + dsw,  b1 + cidx * 16);
        cp16(sbs + 49152 + dsw,  b0 + cidx * 16);
    }
    cp_commit();
}

__global__ __launch_bounds__(256, 1) void k_conv_imma() {
    extern __shared__ __align__(1024) char smem[];
    unsigned sb0 = (unsigned)__cvta_generic_to_shared(smem);

    int t = threadIdx.x;
    int wid = t >> 5;
    int L = t & 31;
    int wm = wid & 3;          // 4 warps along M (o)
    int wn = wid >> 2;         // 2 warps along N (col)
    int colBase = blockIdx.x * 128;
    int oBase = blockIdx.y * 128;

    // ---- fragment (ldmatrix) indexing ----
    int l16 = L & 15;
    unsigned chB = (unsigned)(L >> 4);          // 16B-half selector within k-step
    unsigned fSwz = (unsigned)((l16 & 7) << 4);
    unsigned aRow[2], bRow[4];
#pragma unroll
    for (int mt = 0; mt < 2; mt++) aRow[mt] = (unsigned)((wm * 32 + mt * 16 + l16) * 128);
#pragma unroll
    for (int q = 0; q < 4; q++) bRow[q] = (unsigned)((wn * 64 + q * 16 + l16) * 128);

    int hh[2][8][4], cr[2][8][4];
#pragma unroll
    for (int mt = 0; mt < 2; mt++)
#pragma unroll
        for (int nt = 0; nt < 8; nt++)
#pragma unroll
            for (int qq = 0; qq < 4; qq++) { hh[mt][nt][qq] = 0; cr[mt][nt][qq] = 0; }

    // ---- prologue: stages 0 and 1 ----
    issue_stage(sb0, 0, t);
    issue_stage(sb0 + STAGEB, BK, t);

    // ---- main loop ----
    for (int kt = 0; kt < NIT; kt++) {
        asm volatile("cp.async.wait_group 1;" ::: "memory");
        __syncthreads();

        if (kt + 2 < NIT)
            issue_stage(sb0 + (unsigned)((kt + 2) % 3) * STAGEB, (kt + 2) * BK, t);
        else
            cp_commit();

        unsigned sb = sb0 + (unsigned)(kt % 3) * STAGEB;

#pragma unroll
        for (int ks = 0; ks < 4; ks++) {            // 4 k-steps of 32 bytes
            unsigned ch = ((unsigned)(ks * 2) + chB) << 4;
            unsigned chx = ch ^ fSwz;
            unsigned a1f[2][4], a0f[2][4], b1f[4][4], b0f[4][4];
#pragma unroll
            for (int mt = 0; mt < 2; mt++) {
                ldsm4(a1f[mt], sb + aRow[mt] + chx);
                ldsm4(a0f[mt], sb + 16384 + aRow[mt] + chx);
            }
#pragma unroll
            for (int q = 0; q < 4; q++) {
                ldsm4(b1f[q], sb + 32768 + bRow[q] + chx);
                ldsm4(b0f[q], sb + 49152 + bRow[q] + chx);
            }
#pragma unroll
            for (int mt = 0; mt < 2; mt++)
#pragma unroll
                for (int q = 0; q < 4; q++)
#pragma unroll
                    for (int h = 0; h < 2; h++) {
                        unsigned b1v[2] = {b1f[q][h], b1f[q][h + 2]};
                        unsigned b0v[2] = {b0f[q][h], b0f[q][h + 2]};
                        imma16832(hh[mt][q * 2 + h], a1f[mt], b1v);
                        imma16832(cr[mt][q * 2 + h], a1f[mt], b0v);
                        imma16832(cr[mt][q * 2 + h], a0f[mt], b1v);
                    }
        }
    }

    // ---- epilogue: Yt[col][o] with scales ----
    int gid = L >> 2, tid4 = L & 3;
#pragma unroll
    for (int mt = 0; mt < 2; mt++) {
        int r = oBase + wm * 32 + mt * 16 + gid;
        float sa0 = g_sA[r], sa8 = g_sA[r + 8];
#pragma unroll
        for (int nt = 0; nt < 8; nt++) {
            int c = colBase + wn * 64 + nt * 8 + tid4 * 2;
            float sb0f = g_sB[c], sb1f = g_sB[c + 1];
            float v0 = ((float)hh[mt][nt][0] * 16384.0f + (float)cr[mt][nt][0] * 128.0f) * sa0 * sb0f;
            float v1 = ((float)hh[mt][nt][1] * 16384.0f + (float)cr[mt][nt][1] * 128.0f) * sa0 * sb1f;
            float v2 = ((float)hh[mt][nt][2] * 16384.0f + (float)cr[mt][nt][2] * 128.0f) * sa8 * sb0f;
            float v3 = ((float)hh[mt][nt][3] * 16384.0f + (float)cr[mt][nt][3] * 128.0f) * sa8 * sb1f;
            g_Yt[(size_t)c * CC + r]           = v0;
            g_Yt[(size_t)(c + 1) * CC + r]     = v1;
            g_Yt[(size_t)c * CC + r + 8]       = v2;
            g_Yt[(size_t)(c + 1) * CC + r + 8] = v3;
        }
    }
}

// ---------------------------------------------------------------------------
// Kernel 5: bias + BN + ReLU + residual + LayerNorm(H=16)
// ---------------------------------------------------------------------------
__global__ void k_final(const float* __restrict__ x,
                        const float* __restrict__ conv_b,
                        const float* __restrict__ bn_g, const float* __restrict__ bn_b,
                        const float* __restrict__ bn_m, const float* __restrict__ bn_v,
                        const float* __restrict__ ln_g, const float* __restrict__ ln_b,
                        float* __restrict__ out) {
    int bs = blockIdx.x, n = threadIdx.x;
    size_t base = (size_t)bs * CC + n * HH;
    size_t obase = (size_t)n * HH;

    float v[HH];
#pragma unroll
    for (int h = 0; h < HH; h += 4) {
        float4 y = *(const float4*)&g_Yt[base + h];
        float4 cb = *(const float4*)&conv_b[obase + h];
        float4 bm = *(const float4*)&bn_m[obase + h];
        float4 bvr = *(const float4*)&bn_v[obase + h];
        float4 bg = *(const float4*)&bn_g[obase + h];
        float4 bb = *(const float4*)&bn_b[obase + h];
        float4 xr = *(const float4*)&x[base + h];
        float yy[4] = {y.x, y.y, y.z, y.w};
        float cbv[4] = {cb.x, cb.y, cb.z, cb.w};
        float bmv[4] = {bm.x, bm.y, bm.z, bm.w};
        float bvv[4] = {bvr.x, bvr.y, bvr.z, bvr.w};
        float bgv[4] = {bg.x, bg.y, bg.z, bg.w};
        float bbv[4] = {bb.x, bb.y, bb.z, bb.w};
        float xv[4] = {xr.x, xr.y, xr.z, xr.w};
#pragma unroll
        for (int q = 0; q < 4; q++) {
            float val = yy[q] + cbv[q];
            val = (val - bmv[q]) * rsqrtf(bvv[q] + EPS) * bgv[q] + bbv[q];
            val = fmaxf(val, 0.0f);
            v[h + q] = val + xv[q];
        }
    }

    float mu = 0.0f;
#pragma unroll
    for (int h = 0; h < HH; h++) mu += v[h];
    mu *= (1.0f / HH);
    float var = 0.0f;
#pragma unroll
    for (int h = 0; h < HH; h++) { float dd = v[h] - mu; var += dd * dd; }
    var *= (1.0f / HH);
    float is = rsqrtf(var + EPS);

#pragma unroll
    for (int h = 0; h < HH; h++)
        out[base + h] = (v[h] - mu) * is * ln_g[h] + ln_b[h];
}

// ---------------------------------------------------------------------------
extern "C" void kernel_launch(void* const* d_in, const int* in_sizes, int n_in,
                              void* d_out, int out_size) {
    const float* x      = (const float*)d_in[0];
    const float* adj    = (const float*)d_in[1];
    const float* W      = (const float*)d_in[2];
    const float* a1     = (const float*)d_in[3];
    const float* a2     = (const float*)d_in[4];
    const float* conv_w = (const float*)d_in[5];
    const float* conv_b = (const float*)d_in[6];
    const float* bn_g   = (const float*)d_in[7];
    const float* bn_b   = (const float*)d_in[8];
    const float* bn_m   = (const float*)d_in[9];
    const float* bn_v   = (const float*)d_in[10];
    const float* ln_g   = (const float*)d_in[11];
    const float* ln_b   = (const float*)d_in[12];
    float* out = (float*)d_out;

    cudaFuncSetAttribute(k_conv_imma, cudaFuncAttributeMaxDynamicSharedMemorySize, SMEM_DYN);

    k_mask<<<8, 256>>>(adj);
    k_wh<<<512, 256>>>(x, W, a1, a2);
    k_attn<<<512, 256>>>();
    k_quantA<<<CC, 256>>>(conv_w);
    k_buildB<<<512, 256>>>();
    k_conv_imma<<<dim3(4, 32), 256, SMEM_DYN>>>();
    k_final<<<512, 256>>>(x, conv_b, bn_g, bn_b, bn_m, bn_v, ln_g, ln_b, out);
}

// round 7
// speedup vs baseline: 2.4647x; 2.4647x over previous
#include <cuda_runtime.h>
#include <cuda_fp16.h>
#include <cstdint>

// Problem constants
#define BB 8
#define SS 64
#define NN 256
#define FF 16
#define HH 16
#define CC 4096            // N*H  (= GEMM M)
#define COLS 512           // B*S  (= GEMM Ncol)
#define KTOT 12288         // C*3  (= GEMM K)
#define ALPHA 0.2f
#define EPS 1e-5f

// GEMM tiling (fp16 HMMA, 2-term: D = A*Bhi + A*Blo)
#define BK 64                       // fp16 K per stage (128B rows)
#define TILEB 16384                 // 128 rows x 64 fp16 x 2B, xor-swizzled
#define STAGEB 49152                // A, Bhi, Blo tiles
#define NSTAGE 3
#define NIT (KTOT / BK)             // 192
#define SMEM_DYN (NSTAGE * STAGEB)  // 147456

// ---------------- device scratch (no allocations allowed) -------------------
__device__ float    g_Wh[COLS * NN * HH];
__device__ float    g_f1[COLS * NN];
__device__ float    g_f2[COLS * NN];
__device__ unsigned g_mask[NN * 8];
__device__ float    g_S[(size_t)COLS * CC];        // spatial [col][c]
__device__ __half   g_Af[(size_t)CC * KTOT];       // fp16 weights, 100 MB
__device__ __half   g_Bhi[(size_t)COLS * KTOT];
__device__ __half   g_Blo[(size_t)COLS * KTOT];
__device__ float    g_Yt[(size_t)COLS * CC];       // conv out [col][o]

// ---------------- PTX helpers ----------------------------------------------
__device__ __forceinline__ void cp16(unsigned dst, const void* src) {
    asm volatile("cp.async.cg.shared.global [%0], [%1], 16;" :: "r"(dst), "l"(src) : "memory");
}
__device__ __forceinline__ void cp_commit() {
    asm volatile("cp.async.commit_group;" ::: "memory");
}
__device__ __forceinline__ void ldsm4(unsigned* r, unsigned addr) {
    asm volatile("ldmatrix.sync.aligned.m8n8.x4.shared.b16 {%0,%1,%2,%3}, [%4];"
                 : "=r"(r[0]), "=r"(r[1]), "=r"(r[2]), "=r"(r[3]) : "r"(addr));
}
__device__ __forceinline__ void mma16816h(float* d, const unsigned* a, const unsigned* b) {
    asm volatile(
        "mma.sync.aligned.m16n8k16.row.col.f32.f16.f16.f32 "
        "{%0,%1,%2,%3}, {%4,%5,%6,%7}, {%8,%9}, {%0,%1,%2,%3};"
        : "+f"(d[0]), "+f"(d[1]), "+f"(d[2]), "+f"(d[3])
        : "r"(a[0]), "r"(a[1]), "r"(a[2]), "r"(a[3]), "r"(b[0]), "r"(b[1]));
}

// ---------------------------------------------------------------------------
// Kernel 0: adjacency bitmask
// ---------------------------------------------------------------------------
__global__ void k_mask(const float* __restrict__ adj) {
    int idx = blockIdx.x * blockDim.x + threadIdx.x;
    if (idx >= NN * 8) return;
    int i = idx >> 3, w = idx & 7;
    unsigned m = 0;
#pragma unroll
    for (int b = 0; b < 32; b++)
        if (adj[i * NN + w * 32 + b] > 0.0f) m |= (1u << b);
    g_mask[idx] = m;
}

// ---------------------------------------------------------------------------
// Kernel 1: Wh = x @ W ; f1 = Wh.a1 ; f2 = Wh.a2
// ---------------------------------------------------------------------------
__global__ void k_wh(const float* __restrict__ x, const float* __restrict__ W,
                     const float* __restrict__ a1, const float* __restrict__ a2) {
    __shared__ float sW[FF * HH];
    __shared__ float sa1[HH], sa2[HH];
    int t = threadIdx.x;
    sW[t] = W[t];
    if (t < HH) { sa1[t] = a1[t]; sa2[t] = a2[t]; }
    __syncthreads();

    int bs = blockIdx.x;
    const float* xr = x + (size_t)(bs * NN + t) * FF;
    float xv[FF];
#pragma unroll
    for (int f = 0; f < FF; f += 4) {
        float4 v = *(const float4*)(xr + f);
        xv[f] = v.x; xv[f + 1] = v.y; xv[f + 2] = v.z; xv[f + 3] = v.w;
    }
    float wh[HH];
#pragma unroll
    for (int h = 0; h < HH; h++) wh[h] = 0.0f;
#pragma unroll
    for (int f = 0; f < FF; f++)
#pragma unroll
        for (int h = 0; h < HH; h++) wh[h] += xv[f] * sW[f * HH + h];

    float f1 = 0.0f, f2 = 0.0f;
#pragma unroll
    for (int h = 0; h < HH; h++) { f1 += wh[h] * sa1[h]; f2 += wh[h] * sa2[h]; }

    float* whr = g_Wh + (size_t)(bs * NN + t) * HH;
#pragma unroll
    for (int h = 0; h < HH; h += 4)
        *(float4*)(whr + h) = make_float4(wh[h], wh[h + 1], wh[h + 2], wh[h + 3]);
    g_f1[bs * NN + t] = f1;
    g_f2[bs * NN + t] = f2;
}

// ---------------------------------------------------------------------------
// Kernel 2: attention softmax + spatial = attn @ Wh -> g_S[col][c]
// ---------------------------------------------------------------------------
__global__ void k_attn() {
    __shared__ float    sWh[NN * HH];
    __shared__ float    sf2[NN];
    __shared__ unsigned smask[NN * 8];

    int bs = blockIdx.x;
    int t = threadIdx.x;

    for (int idx = t; idx < NN * HH; idx += 256) sWh[idx] = g_Wh[(size_t)bs * NN * HH + idx];
    sf2[t] = g_f2[bs * NN + t];
    for (int idx = t; idx < NN * 8; idx += 256) smask[idx] = g_mask[idx];
    __syncthreads();

    float f1i = g_f1[bs * NN + t];

    float m = -1e30f;
#pragma unroll 1
    for (int jw = 0; jw < 8; jw++) {
        unsigned wd = smask[t * 8 + jw];
#pragma unroll
        for (int bit = 0; bit < 32; bit++) {
            float e = f1i + sf2[jw * 32 + bit];
            e = e > 0.0f ? e : ALPHA * e;
            if ((wd >> bit) & 1u) m = fmaxf(m, e);
        }
    }

    float sum = 0.0f;
    float acc[HH];
#pragma unroll
    for (int h = 0; h < HH; h++) acc[h] = 0.0f;

#pragma unroll 1
    for (int jw = 0; jw < 8; jw++) {
        unsigned wd = smask[t * 8 + jw];
#pragma unroll
        for (int bit = 0; bit < 32; bit++) {
            int j = jw * 32 + bit;
            float e = f1i + sf2[j];
            e = e > 0.0f ? e : ALPHA * e;
            float w = ((wd >> bit) & 1u) ? __expf(e - m) : 0.0f;
            sum += w;
#pragma unroll
            for (int h = 0; h < HH; h++) acc[h] += w * sWh[j * HH + h];
        }
    }

    float inv = 1.0f / sum;
    float* so = g_S + (size_t)bs * CC + t * HH;
#pragma unroll
    for (int h = 0; h < HH; h += 4)
        *(float4*)(so + h) = make_float4(acc[h] * inv, acc[h + 1] * inv,
                                         acc[h + 2] * inv, acc[h + 3] * inv);
}

// ---------------------------------------------------------------------------
// Kernel 3a: convert conv weights fp32 -> fp16 (single limb)
// ---------------------------------------------------------------------------
__global__ void k_cvtA(const float* __restrict__ w) {
    size_t i = ((size_t)blockIdx.x * 256 + threadIdx.x) * 8;
    float4 v0 = *(const float4*)(w + i);
    float4 v1 = *(const float4*)(w + i + 4);
    __half h[8];
    h[0] = __float2half_rn(v0.x); h[1] = __float2half_rn(v0.y);
    h[2] = __float2half_rn(v0.z); h[3] = __float2half_rn(v0.w);
    h[4] = __float2half_rn(v1.x); h[5] = __float2half_rn(v1.y);
    h[6] = __float2half_rn(v1.z); h[7] = __float2half_rn(v1.w);
    *reinterpret_cast<uint4*>(g_Af + i) = *reinterpret_cast<uint4*>(h);
}

// ---------------------------------------------------------------------------
// Kernel 3b: build B (K-major, [col][c*3+tap]) as exact fp16 2-limb split.
// ---------------------------------------------------------------------------
__global__ void k_buildB() {
    int col = blockIdx.x;           // 0..511
    int s = col & 63;
    for (int c = threadIdx.x; c < CC; c += 256) {
        float vm = (s > 0)  ? g_S[(size_t)(col - 1) * CC + c] : 0.0f;
        float v0 =            g_S[(size_t)col * CC + c];
        float vp = (s < 63) ? g_S[(size_t)(col + 1) * CC + c] : 0.0f;
        float t3[3] = {vm, v0, vp};
        size_t base = (size_t)col * KTOT + 3 * (size_t)c;
#pragma unroll
        for (int tap = 0; tap < 3; tap++) {
            __half h = __float2half_rn(t3[tap]);
            __half l = __float2half_rn(t3[tap] - __half2float(h));
            g_Bhi[base + tap] = h;
            g_Blo[base + tap] = l;
        }
    }
}

// ---------------------------------------------------------------------------
// Kernel 4: fp16 HMMA 2-term GEMM. D[o][col] = A[o][:] . (Bhi+Blo)[col][:]
// 128x128 CTA tile, BK=64, 3 stages, 8 warps (4M x 2N), warp tile m32n64.
// ---------------------------------------------------------------------------
__device__ __forceinline__ void issue_stage(unsigned sbs, int kb, int t,
                                            const __half* aG,
                                            const __half* bHg,
                                            const __half* bLg) {
    int row = t >> 1;                   // 0..127
    int h2 = t & 1;
    unsigned rowB = (unsigned)(row * 128);
    unsigned swz = (unsigned)((row & 7) << 4);
    size_t go = (size_t)row * KTOT + kb;
#pragma unroll
    for (int j = 0; j < 4; j++) {
        int cidx = j * 2 + h2;
        unsigned dsw = rowB + (((unsigned)(cidx * 16)) ^ swz);
        size_t gs = go + cidx * 8;
        cp16(sbs + dsw,          aG + gs);
        cp16(sbs + 16384 + dsw,  bHg + gs);
        cp16(sbs + 32768 + dsw,  bLg + gs);
    }
    cp_commit();
}

__global__ __launch_bounds__(256, 1) void k_conv_mma() {
    extern __shared__ __align__(1024) char smem[];
    unsigned sb0 = (unsigned)__cvta_generic_to_shared(smem);

    int t = threadIdx.x;
    int wid = t >> 5;
    int L = t & 31;
    int wm = wid & 3;          // 4 warps along M (o)
    int wn = wid >> 2;         // 2 warps along N (col)
    int colBase = blockIdx.x * 128;
    int oBase = blockIdx.y * 128;

    const __half* aG  = g_Af  + (size_t)oBase * KTOT;
    const __half* bHg = g_Bhi + (size_t)colBase * KTOT;
    const __half* bLg = g_Blo + (size_t)colBase * KTOT;

    // ---- fragment (ldmatrix) indexing ----
    int l16 = L & 15;
    unsigned chB = (unsigned)(L >> 4);          // k-half selector
    unsigned fSwz = (unsigned)((l16 & 7) << 4); // row%8 xor bits (tiles 16-row aligned)
    unsigned aRow[2], bRow[4];
#pragma unroll
    for (int mt = 0; mt < 2; mt++) aRow[mt] = (unsigned)((wm * 32 + mt * 16 + l16) * 128);
#pragma unroll
    for (int q = 0; q < 4; q++) bRow[q] = (unsigned)((wn * 64 + q * 16 + l16) * 128);

    float d[2][8][4];
#pragma unroll
    for (int mt = 0; mt < 2; mt++)
#pragma unroll
        for (int nt = 0; nt < 8; nt++)
#pragma unroll
            for (int qq = 0; qq < 4; qq++) d[mt][nt][qq] = 0.0f;

    // ---- prologue: stages 0 and 1 ----
    issue_stage(sb0, 0, t, aG, bHg, bLg);
    issue_stage(sb0 + STAGEB, BK, t, aG, bHg, bLg);

    // ---- main loop ----
    for (int kt = 0; kt < NIT; kt++) {
        asm volatile("cp.async.wait_group 1;" ::: "memory");
        __syncthreads();

        if (kt + 2 < NIT)
            issue_stage(sb0 + (unsigned)((kt + 2) % 3) * STAGEB, (kt + 2) * BK,
                        t, aG, bHg, bLg);
        else
            cp_commit();

        unsigned sb = sb0 + (unsigned)(kt % 3) * STAGEB;

#pragma unroll
        for (int ks = 0; ks < 4; ks++) {
            unsigned ch = ((unsigned)(ks * 2) + chB) << 4;
            unsigned chx = ch ^ fSwz;
            unsigned af[2][4], bhf[4][4], blf[4][4];
#pragma unroll
            for (int mt = 0; mt < 2; mt++)
                ldsm4(af[mt], sb + aRow[mt] + chx);
#pragma unroll
            for (int q = 0; q < 4; q++) {
                ldsm4(bhf[q], sb + 16384 + bRow[q] + chx);
                ldsm4(blf[q], sb + 32768 + bRow[q] + chx);
            }
#pragma unroll
            for (int mt = 0; mt < 2; mt++)
#pragma unroll
                for (int q = 0; q < 4; q++)
#pragma unroll
                    for (int h = 0; h < 2; h++) {
                        unsigned bhv[2] = {bhf[q][h], bhf[q][h + 2]};
                        unsigned blv[2] = {blf[q][h], blf[q][h + 2]};
                        float* dd = d[mt][q * 2 + h];
                        mma16816h(dd, af[mt], bhv);
                        mma16816h(dd, af[mt], blv);
                    }
        }
    }

    // ---- epilogue: Yt[col][o] ----
    int gid = L >> 2, tid4 = L & 3;
#pragma unroll
    for (int mt = 0; mt < 2; mt++) {
        int r = oBase + wm * 32 + mt * 16 + gid;
#pragma unroll
        for (int nt = 0; nt < 8; nt++) {
            int c = colBase + wn * 64 + nt * 8 + tid4 * 2;
            g_Yt[(size_t)c * CC + r]           = d[mt][nt][0];
            g_Yt[(size_t)(c + 1) * CC + r]     = d[mt][nt][1];
            g_Yt[(size_t)c * CC + r + 8]       = d[mt][nt][2];
            g_Yt[(size_t)(c + 1) * CC + r + 8] = d[mt][nt][3];
        }
    }
}

// ---------------------------------------------------------------------------
// Kernel 5: bias + BN + ReLU + residual + LayerNorm(H=16)
// ---------------------------------------------------------------------------
__global__ void k_final(const float* __restrict__ x,
                        const float* __restrict__ conv_b,
                        const float* __restrict__ bn_g, const float* __restrict__ bn_b,
                        const float* __restrict__ bn_m, const float* __restrict__ bn_v,
                        const float* __restrict__ ln_g, const float* __restrict__ ln_b,
                        float* __restrict__ out) {
    int bs = blockIdx.x, n = threadIdx.x;
    size_t base = (size_t)bs * CC + n * HH;
    size_t obase = (size_t)n * HH;

    float v[HH];
#pragma unroll
    for (int h = 0; h < HH; h += 4) {
        float4 y = *(const float4*)&g_Yt[base + h];
        float4 cb = *(const float4*)&conv_b[obase + h];
        float4 bm = *(const float4*)&bn_m[obase + h];
        float4 bvr = *(const float4*)&bn_v[obase + h];
        float4 bg = *(const float4*)&bn_g[obase + h];
        float4 bb = *(const float4*)&bn_b[obase + h];
        float4 xr = *(const float4*)&x[base + h];
        float yy[4] = {y.x, y.y, y.z, y.w};
        float cbv[4] = {cb.x, cb.y, cb.z, cb.w};
        float bmv[4] = {bm.x, bm.y, bm.z, bm.w};
        float bvv[4] = {bvr.x, bvr.y, bvr.z, bvr.w};
        float bgv[4] = {bg.x, bg.y, bg.z, bg.w};
        float bbv[4] = {bb.x, bb.y, bb.z, bb.w};
        float xv[4] = {xr.x, xr.y, xr.z, xr.w};
#pragma unroll
        for (int q = 0; q < 4; q++) {
            float val = yy[q] + cbv[q];
            val = (val - bmv[q]) * rsqrtf(bvv[q] + EPS) * bgv[q] + bbv[q];
            val = fmaxf(val, 0.0f);
            v[h + q] = val + xv[q];
        }
    }

    float mu = 0.0f;
#pragma unroll
    for (int h = 0; h < HH; h++) mu += v[h];
    mu *= (1.0f / HH);
    float var = 0.0f;
#pragma unroll
    for (int h = 0; h < HH; h++) { float dd = v[h] - mu; var += dd * dd; }
    var *= (1.0f / HH);
    float is = rsqrtf(var + EPS);

#pragma unroll
    for (int h = 0; h < HH; h++)
        out[base + h] = (v[h] - mu) * is * ln_g[h] + ln_b[h];
}

// ---------------------------------------------------------------------------
extern "C" void kernel_launch(void* const* d_in, const int* in_sizes, int n_in,
                              void* d_out, int out_size) {
    const float* x      = (const float*)d_in[0];
    const float* adj    = (const float*)d_in[1];
    const float* W      = (const float*)d_in[2];
    const float* a1     = (const float*)d_in[3];
    const float* a2     = (const float*)d_in[4];
    const float* conv_w = (const float*)d_in[5];
    const float* conv_b = (const float*)d_in[6];
    const float* bn_g   = (const float*)d_in[7];
    const float* bn_b   = (const float*)d_in[8];
    const float* bn_m   = (const float*)d_in[9];
    const float* bn_v   = (const float*)d_in[10];
    const float* ln_g   = (const float*)d_in[11];
    const float* ln_b   = (const float*)d_in[12];
    float* out = (float*)d_out;

    cudaFuncSetAttribute(k_conv_mma, cudaFuncAttributeMaxDynamicSharedMemorySize, SMEM_DYN);

    k_mask<<<8, 256>>>(adj);
    k_wh<<<512, 256>>>(x, W, a1, a2);
    k_attn<<<512, 256>>>();
    k_cvtA<<<24576, 256>>>(conv_w);     // 4096*12288/(256*8)
    k_buildB<<<512, 256>>>();
    k_conv_mma<<<dim3(4, 32), 256, SMEM_DYN>>>();
    k_final<<<512, 256>>>(x, conv_b, bn_g, bn_b, bn_m, bn_v, ln_g, ln_b, out);
}

// round 8
// speedup vs baseline: 3.7034x; 1.5026x over previous
#include <cuda_runtime.h>
#include <cuda_fp16.h>
#include <cstdint>

// Problem constants
#define BB 8
#define SS 64
#define NN 256
#define FF 16
#define HH 16
#define CC 4096            // N*H  (= GEMM M)
#define COLS 512           // B*S  (= GEMM Ncol)
#define KTOT 12288         // C*3  (= GEMM K)
#define ALPHA 0.2f
#define EPS 1e-5f

// GEMM tiling (fp16 HMMA, single-term: D = A*B)
#define BK 64                       // fp16 K per stage (128B rows)
#define TILEB 16384                 // 128 rows x 64 fp16 x 2B, xor-swizzled
#define STAGEB 32768                // A, B tiles
#define NSTAGE 3
#define NIT (KTOT / BK)             // 192
#define SMEM_DYN (NSTAGE * STAGEB)  // 98304

// ---------------- device scratch (no allocations allowed) -------------------
__device__ float    g_Wh[COLS * NN * HH];
__device__ float    g_f1[COLS * NN];
__device__ float    g_f2[COLS * NN];
__device__ unsigned g_mask[NN * 8];
__device__ float    g_S[(size_t)COLS * CC];        // spatial [col][c]
__device__ __half   g_Af[(size_t)CC * KTOT];       // fp16 weights, 100 MB
__device__ __half   g_Bf[(size_t)COLS * KTOT];     // fp16 data, 12.6 MB
__device__ float    g_Yt[(size_t)COLS * CC];       // conv out [col][o]

// ---------------- PTX helpers ----------------------------------------------
__device__ __forceinline__ void cp16(unsigned dst, const void* src) {
    asm volatile("cp.async.cg.shared.global [%0], [%1], 16;" :: "r"(dst), "l"(src) : "memory");
}
__device__ __forceinline__ void cp_commit() {
    asm volatile("cp.async.commit_group;" ::: "memory");
}
__device__ __forceinline__ void ldsm4(unsigned* r, unsigned addr) {
    asm volatile("ldmatrix.sync.aligned.m8n8.x4.shared.b16 {%0,%1,%2,%3}, [%4];"
                 : "=r"(r[0]), "=r"(r[1]), "=r"(r[2]), "=r"(r[3]) : "r"(addr));
}
__device__ __forceinline__ void mma16816h(float* d, const unsigned* a, const unsigned* b) {
    asm volatile(
        "mma.sync.aligned.m16n8k16.row.col.f32.f16.f16.f32 "
        "{%0,%1,%2,%3}, {%4,%5,%6,%7}, {%8,%9}, {%0,%1,%2,%3};"
        : "+f"(d[0]), "+f"(d[1]), "+f"(d[2]), "+f"(d[3])
        : "r"(a[0]), "r"(a[1]), "r"(a[2]), "r"(a[3]), "r"(b[0]), "r"(b[1]));
}

// ---------------------------------------------------------------------------
// Kernel 0: adjacency bitmask
// ---------------------------------------------------------------------------
__global__ void k_mask(const float* __restrict__ adj) {
    int idx = blockIdx.x * blockDim.x + threadIdx.x;
    if (idx >= NN * 8) return;
    int i = idx >> 3, w = idx & 7;
    unsigned m = 0;
#pragma unroll
    for (int b = 0; b < 32; b++)
        if (adj[i * NN + w * 32 + b] > 0.0f) m |= (1u << b);
    g_mask[idx] = m;
}

// ---------------------------------------------------------------------------
// Kernel 1: Wh = x @ W ; f1 = Wh.a1 ; f2 = Wh.a2
// ---------------------------------------------------------------------------
__global__ void k_wh(const float* __restrict__ x, const float* __restrict__ W,
                     const float* __restrict__ a1, const float* __restrict__ a2) {
    __shared__ float sW[FF * HH];
    __shared__ float sa1[HH], sa2[HH];
    int t = threadIdx.x;
    sW[t] = W[t];
    if (t < HH) { sa1[t] = a1[t]; sa2[t] = a2[t]; }
    __syncthreads();

    int bs = blockIdx.x;
    const float* xr = x + (size_t)(bs * NN + t) * FF;
    float xv[FF];
#pragma unroll
    for (int f = 0; f < FF; f += 4) {
        float4 v = *(const float4*)(xr + f);
        xv[f] = v.x; xv[f + 1] = v.y; xv[f + 2] = v.z; xv[f + 3] = v.w;
    }
    float wh[HH];
#pragma unroll
    for (int h = 0; h < HH; h++) wh[h] = 0.0f;
#pragma unroll
    for (int f = 0; f < FF; f++)
#pragma unroll
        for (int h = 0; h < HH; h++) wh[h] += xv[f] * sW[f * HH + h];

    float f1 = 0.0f, f2 = 0.0f;
#pragma unroll
    for (int h = 0; h < HH; h++) { f1 += wh[h] * sa1[h]; f2 += wh[h] * sa2[h]; }

    float* whr = g_Wh + (size_t)(bs * NN + t) * HH;
#pragma unroll
    for (int h = 0; h < HH; h += 4)
        *(float4*)(whr + h) = make_float4(wh[h], wh[h + 1], wh[h + 2], wh[h + 3]);
    g_f1[bs * NN + t] = f1;
    g_f2[bs * NN + t] = f2;
}

// ---------------------------------------------------------------------------
// Kernel 2: attention softmax + spatial = attn @ Wh -> g_S[col][c]
// ---------------------------------------------------------------------------
__global__ void k_attn() {
    __shared__ float    sWh[NN * HH];
    __shared__ float    sf2[NN];
    __shared__ unsigned smask[NN * 8];

    int bs = blockIdx.x;
    int t = threadIdx.x;

    for (int idx = t; idx < NN * HH; idx += 256) sWh[idx] = g_Wh[(size_t)bs * NN * HH + idx];
    sf2[t] = g_f2[bs * NN + t];
    for (int idx = t; idx < NN * 8; idx += 256) smask[idx] = g_mask[idx];
    __syncthreads();

    float f1i = g_f1[bs * NN + t];

    float m = -1e30f;
#pragma unroll 1
    for (int jw = 0; jw < 8; jw++) {
        unsigned wd = smask[t * 8 + jw];
#pragma unroll
        for (int bit = 0; bit < 32; bit++) {
            float e = f1i + sf2[jw * 32 + bit];
            e = e > 0.0f ? e : ALPHA * e;
            if ((wd >> bit) & 1u) m = fmaxf(m, e);
        }
    }

    float sum = 0.0f;
    float acc[HH];
#pragma unroll
    for (int h = 0; h < HH; h++) acc[h] = 0.0f;

#pragma unroll 1
    for (int jw = 0; jw < 8; jw++) {
        unsigned wd = smask[t * 8 + jw];
#pragma unroll
        for (int bit = 0; bit < 32; bit++) {
            int j = jw * 32 + bit;
            float e = f1i + sf2[j];
            e = e > 0.0f ? e : ALPHA * e;
            float w = ((wd >> bit) & 1u) ? __expf(e - m) : 0.0f;
            sum += w;
#pragma unroll
            for (int h = 0; h < HH; h++) acc[h] += w * sWh[j * HH + h];
        }
    }

    float inv = 1.0f / sum;
    float* so = g_S + (size_t)bs * CC + t * HH;
#pragma unroll
    for (int h = 0; h < HH; h += 4)
        *(float4*)(so + h) = make_float4(acc[h] * inv, acc[h + 1] * inv,
                                         acc[h + 2] * inv, acc[h + 3] * inv);
}

// ---------------------------------------------------------------------------
// Kernel 3a: convert conv weights fp32 -> fp16
// ---------------------------------------------------------------------------
__global__ void k_cvtA(const float* __restrict__ w) {
    size_t i = ((size_t)blockIdx.x * 256 + threadIdx.x) * 8;
    float4 v0 = *(const float4*)(w + i);
    float4 v1 = *(const float4*)(w + i + 4);
    __half h[8];
    h[0] = __float2half_rn(v0.x); h[1] = __float2half_rn(v0.y);
    h[2] = __float2half_rn(v0.z); h[3] = __float2half_rn(v0.w);
    h[4] = __float2half_rn(v1.x); h[5] = __float2half_rn(v1.y);
    h[6] = __float2half_rn(v1.z); h[7] = __float2half_rn(v1.w);
    *reinterpret_cast<uint4*>(g_Af + i) = *reinterpret_cast<uint4*>(h);
}

// ---------------------------------------------------------------------------
// Kernel 3b: build B (K-major, [col][c*3+tap]) in fp16 from g_S.
// ---------------------------------------------------------------------------
__global__ void k_buildB() {
    int col = blockIdx.x;           // 0..511
    int s = col & 63;
    for (int c = threadIdx.x; c < CC; c += 256) {
        float vm = (s > 0)  ? g_S[(size_t)(col - 1) * CC + c] : 0.0f;
        float v0 =            g_S[(size_t)col * CC + c];
        float vp = (s < 63) ? g_S[(size_t)(col + 1) * CC + c] : 0.0f;
        size_t base = (size_t)col * KTOT + 3 * (size_t)c;
        g_Bf[base]     = __float2half_rn(vm);
        g_Bf[base + 1] = __float2half_rn(v0);
        g_Bf[base + 2] = __float2half_rn(vp);
    }
}

// ---------------------------------------------------------------------------
// Kernel 4: fp16 HMMA GEMM. D[o][col] = A[o][:] . B[col][:]
// 128x128 CTA tile, BK=64, 3 stages, 8 warps (4M x 2N), warp tile m32n64.
// ---------------------------------------------------------------------------
__device__ __forceinline__ void issue_stage(unsigned sbs, int kb, int t,
                                            const __half* aG, const __half* bG) {
    int row = t >> 1;                   // 0..127
    int h2 = t & 1;
    unsigned rowB = (unsigned)(row * 128);
    unsigned swz = (unsigned)((row & 7) << 4);
    size_t go = (size_t)row * KTOT + kb;
#pragma unroll
    for (int j = 0; j < 4; j++) {
        int cidx = j * 2 + h2;
        unsigned dsw = rowB + (((unsigned)(cidx * 16)) ^ swz);
        size_t gs = go + cidx * 8;
        cp16(sbs + dsw,          aG + gs);
        cp16(sbs + 16384 + dsw,  bG + gs);
    }
    cp_commit();
}

__global__ __launch_bounds__(256, 1) void k_conv_mma() {
    extern __shared__ __align__(1024) char smem[];
    unsigned sb0 = (unsigned)__cvta_generic_to_shared(smem);

    int t = threadIdx.x;
    int wid = t >> 5;
    int L = t & 31;
    int wm = wid & 3;          // 4 warps along M (o)
    int wn = wid >> 2;         // 2 warps along N (col)
    int colBase = blockIdx.x * 128;
    int oBase = blockIdx.y * 128;

    const __half* aG = g_Af + (size_t)oBase * KTOT;
    const __half* bG = g_Bf + (size_t)colBase * KTOT;

    // ---- fragment (ldmatrix) indexing ----
    int l16 = L & 15;
    unsigned chB = (unsigned)(L >> 4);          // k-half selector
    unsigned fSwz = (unsigned)((l16 & 7) << 4); // row%8 xor bits (tiles 16-row aligned)
    unsigned aRow[2], bRow[4];
#pragma unroll
    for (int mt = 0; mt < 2; mt++) aRow[mt] = (unsigned)((wm * 32 + mt * 16 + l16) * 128);
#pragma unroll
    for (int q = 0; q < 4; q++) bRow[q] = (unsigned)((wn * 64 + q * 16 + l16) * 128);

    float d[2][8][4];
#pragma unroll
    for (int mt = 0; mt < 2; mt++)
#pragma unroll
        for (int nt = 0; nt < 8; nt++)
#pragma unroll
            for (int qq = 0; qq < 4; qq++) d[mt][nt][qq] = 0.0f;

    // ---- prologue: stages 0 and 1 ----
    issue_stage(sb0, 0, t, aG, bG);
    issue_stage(sb0 + STAGEB, BK, t, aG, bG);

    // ---- main loop ----
    for (int kt = 0; kt < NIT; kt++) {
        asm volatile("cp.async.wait_group 1;" ::: "memory");
        __syncthreads();

        if (kt + 2 < NIT)
            issue_stage(sb0 + (unsigned)((kt + 2) % 3) * STAGEB, (kt + 2) * BK,
                        t, aG, bG);
        else
            cp_commit();

        unsigned sb = sb0 + (unsigned)(kt % 3) * STAGEB;

#pragma unroll
        for (int ks = 0; ks < 4; ks++) {
            unsigned ch = ((unsigned)(ks * 2) + chB) << 4;
            unsigned chx = ch ^ fSwz;
            unsigned af[2][4], bf[4][4];
#pragma unroll
            for (int mt = 0; mt < 2; mt++)
                ldsm4(af[mt], sb + aRow[mt] + chx);
#pragma unroll
            for (int q = 0; q < 4; q++)
                ldsm4(bf[q], sb + 16384 + bRow[q] + chx);
#pragma unroll
            for (int mt = 0; mt < 2; mt++)
#pragma unroll
                for (int q = 0; q < 4; q++)
#pragma unroll
                    for (int h = 0; h < 2; h++) {
                        unsigned bv[2] = {bf[q][h], bf[q][h + 2]};
                        mma16816h(d[mt][q * 2 + h], af[mt], bv);
                    }
        }
    }

    // ---- epilogue: Yt[col][o] ----
    int gid = L >> 2, tid4 = L & 3;
#pragma unroll
    for (int mt = 0; mt < 2; mt++) {
        int r = oBase + wm * 32 + mt * 16 + gid;
#pragma unroll
        for (int nt = 0; nt < 8; nt++) {
            int c = colBase + wn * 64 + nt * 8 + tid4 * 2;
            g_Yt[(size_t)c * CC + r]           = d[mt][nt][0];
            g_Yt[(size_t)(c + 1) * CC + r]     = d[mt][nt][1];
            g_Yt[(size_t)c * CC + r + 8]       = d[mt][nt][2];
            g_Yt[(size_t)(c + 1) * CC + r + 8] = d[mt][nt][3];
        }
    }
}

// ---------------------------------------------------------------------------
// Kernel 5: bias + BN + ReLU + residual + LayerNorm(H=16)
// ---------------------------------------------------------------------------
__global__ void k_final(const float* __restrict__ x,
                        const float* __restrict__ conv_b,
                        const float* __restrict__ bn_g, const float* __restrict__ bn_b,
                        const float* __restrict__ bn_m, const float* __restrict__ bn_v,
                        const float* __restrict__ ln_g, const float* __restrict__ ln_b,
                        float* __restrict__ out) {
    int bs = blockIdx.x, n = threadIdx.x;
    size_t base = (size_t)bs * CC + n * HH;
    size_t obase = (size_t)n * HH;

    float v[HH];
#pragma unroll
    for (int h = 0; h < HH; h += 4) {
        float4 y = *(const float4*)&g_Yt[base + h];
        float4 cb = *(const float4*)&conv_b[obase + h];
        float4 bm = *(const float4*)&bn_m[obase + h];
        float4 bvr = *(const float4*)&bn_v[obase + h];
        float4 bg = *(const float4*)&bn_g[obase + h];
        float4 bb = *(const float4*)&bn_b[obase + h];
        float4 xr = *(const float4*)&x[base + h];
        float yy[4] = {y.x, y.y, y.z, y.w};
        float cbv[4] = {cb.x, cb.y, cb.z, cb.w};
        float bmv[4] = {bm.x, bm.y, bm.z, bm.w};
        float bvv[4] = {bvr.x, bvr.y, bvr.z, bvr.w};
        float bgv[4] = {bg.x, bg.y, bg.z, bg.w};
        float bbv[4] = {bb.x, bb.y, bb.z, bb.w};
        float xv[4] = {xr.x, xr.y, xr.z, xr.w};
#pragma unroll
        for (int q = 0; q < 4; q++) {
            float val = yy[q] + cbv[q];
            val = (val - bmv[q]) * rsqrtf(bvv[q] + EPS) * bgv[q] + bbv[q];
            val = fmaxf(val, 0.0f);
            v[h + q] = val + xv[q];
        }
    }

    float mu = 0.0f;
#pragma unroll
    for (int h = 0; h < HH; h++) mu += v[h];
    mu *= (1.0f / HH);
    float var = 0.0f;
#pragma unroll
    for (int h = 0; h < HH; h++) { float dd = v[h] - mu; var += dd * dd; }
    var *= (1.0f / HH);
    float is = rsqrtf(var + EPS);

#pragma unroll
    for (int h = 0; h < HH; h++)
        out[base + h] = (v[h] - mu) * is * ln_g[h] + ln_b[h];
}

// ---------------------------------------------------------------------------
extern "C" void kernel_launch(void* const* d_in, const int* in_sizes, int n_in,
                              void* d_out, int out_size) {
    const float* x      = (const float*)d_in[0];
    const float* adj    = (const float*)d_in[1];
    const float* W      = (const float*)d_in[2];
    const float* a1     = (const float*)d_in[3];
    const float* a2     = (const float*)d_in[4];
    const float* conv_w = (const float*)d_in[5];
    const float* conv_b = (const float*)d_in[6];
    const float* bn_g   = (const float*)d_in[7];
    const float* bn_b   = (const float*)d_in[8];
    const float* bn_m   = (const float*)d_in[9];
    const float* bn_v   = (const float*)d_in[10];
    const float* ln_g   = (const float*)d_in[11];
    const float* ln_b   = (const float*)d_in[12];
    float* out = (float*)d_out;

    cudaFuncSetAttribute(k_conv_mma, cudaFuncAttributeMaxDynamicSharedMemorySize, SMEM_DYN);

    k_mask<<<8, 256>>>(adj);
    k_wh<<<512, 256>>>(x, W, a1, a2);
    k_attn<<<512, 256>>>();
    k_cvtA<<<24576, 256>>>(conv_w);     // 4096*12288/(256*8)
    k_buildB<<<512, 256>>>();
    k_conv_mma<<<dim3(4, 32), 256, SMEM_DYN>>>();
    k_final<<<512, 256>>>(x, conv_b, bn_g, bn_b, bn_m, bn_v, ln_g, ln_b, out);
}

// round 9
// speedup vs baseline: 4.1725x; 1.1267x over previous
#include <cuda_runtime.h>
#include <cuda_fp16.h>
#include <cstdint>

// Problem constants
#define BB 8
#define SS 64
#define NN 256
#define FF 16
#define HH 16
#define CC 4096            // N*H  (= GEMM M)
#define COLS 512           // B*S  (= GEMM Ncol)
#define KTOT 12288         // C*3  (= GEMM K)
#define ALPHA 0.2f
#define EPS 1e-5f

// GEMM tiling (fp16 HMMA, single-term: D = A*B); K is tap-major: k = tap*4096 + c
#define BK 64                       // fp16 K per stage (128B rows)
#define TILEB 16384                 // 128 rows x 64 fp16 x 2B, xor-swizzled
#define STAGEB 32768                // A, B tiles
#define NSTAGE 3
#define NIT (KTOT / BK)             // 192
#define SMEM_DYN (NSTAGE * STAGEB)  // 98304

#define GAT_BLOCKS 512
#define CVT_BLOCKS 16384            // 4096*1024 threads, 4 channels each

// ---------------- device scratch (no allocations allowed) -------------------
__device__ unsigned g_mask[NN * 8];
__device__ __half   g_Af[(size_t)CC * KTOT];       // fp16 weights (tap-major K)
__device__ __half   g_Bf[(size_t)COLS * KTOT];     // fp16 data (tap-major K)
__device__ float    g_Yt[(size_t)COLS * CC];       // conv out [col][o]

// ---------------- PTX helpers ----------------------------------------------
__device__ __forceinline__ void cp16(unsigned dst, const void* src) {
    asm volatile("cp.async.cg.shared.global [%0], [%1], 16;" :: "r"(dst), "l"(src) : "memory");
}
__device__ __forceinline__ void cp_commit() {
    asm volatile("cp.async.commit_group;" ::: "memory");
}
__device__ __forceinline__ void ldsm4(unsigned* r, unsigned addr) {
    asm volatile("ldmatrix.sync.aligned.m8n8.x4.shared.b16 {%0,%1,%2,%3}, [%4];"
                 : "=r"(r[0]), "=r"(r[1]), "=r"(r[2]), "=r"(r[3]) : "r"(addr));
}
__device__ __forceinline__ void mma16816h(float* d, const unsigned* a, const unsigned* b) {
    asm volatile(
        "mma.sync.aligned.m16n8k16.row.col.f32.f16.f16.f32 "
        "{%0,%1,%2,%3}, {%4,%5,%6,%7}, {%8,%9}, {%0,%1,%2,%3};"
        : "+f"(d[0]), "+f"(d[1]), "+f"(d[2]), "+f"(d[3])
        : "r"(a[0]), "r"(a[1]), "r"(a[2]), "r"(a[3]), "r"(b[0]), "r"(b[1]));
}

// ---------------------------------------------------------------------------
// Kernel 0: adjacency bitmask
// ---------------------------------------------------------------------------
__global__ void k_mask(const float* __restrict__ adj) {
    int idx = blockIdx.x * blockDim.x + threadIdx.x;
    if (idx >= NN * 8) return;
    int i = idx >> 3, w = idx & 7;
    unsigned m = 0;
#pragma unroll
    for (int b = 0; b < 32; b++)
        if (adj[i * NN + w * 32 + b] > 0.0f) m |= (1u << b);
    g_mask[idx] = m;
}

// ---------------------------------------------------------------------------
// Fat kernel: blocks [0,512) = GAT (wh+attn+softmax+spatial+B scatter),
//             blocks [512, 512+16384) = weight convert fp32 -> fp16 tap-major.
// ---------------------------------------------------------------------------
__device__ void gat_body(int bs, const float* __restrict__ x,
                         const float* __restrict__ W,
                         const float* __restrict__ a1v,
                         const float* __restrict__ a2v) {
    __shared__ float    sW[FF * HH];
    __shared__ float    sa1[HH], sa2[HH];
    __shared__ float    sWh[NN * HH];
    __shared__ float    sf2[NN];
    __shared__ unsigned smask[NN * 8];

    int t = threadIdx.x;
    sW[t] = W[t];
    if (t < HH) { sa1[t] = a1v[t]; sa2[t] = a2v[t]; }
    for (int idx = t; idx < NN * 8; idx += 256) smask[idx] = g_mask[idx];
    __syncthreads();

    // ---- Wh = x @ W ; f1, f2 ----
    const float* xr = x + (size_t)(bs * NN + t) * FF;
    float xv[FF];
#pragma unroll
    for (int f = 0; f < FF; f += 4) {
        float4 v = *(const float4*)(xr + f);
        xv[f] = v.x; xv[f + 1] = v.y; xv[f + 2] = v.z; xv[f + 3] = v.w;
    }
    float wh[HH];
#pragma unroll
    for (int h = 0; h < HH; h++) wh[h] = 0.0f;
#pragma unroll
    for (int f = 0; f < FF; f++)
#pragma unroll
        for (int h = 0; h < HH; h++) wh[h] += xv[f] * sW[f * HH + h];

    float f1i = 0.0f, f2i = 0.0f;
#pragma unroll
    for (int h = 0; h < HH; h++) { f1i += wh[h] * sa1[h]; f2i += wh[h] * sa2[h]; }

#pragma unroll
    for (int h = 0; h < HH; h++) sWh[t * HH + h] = wh[h];
    sf2[t] = f2i;
    __syncthreads();

    // ---- masked softmax: pass 1 max ----
    float m = -1e30f;
#pragma unroll 1
    for (int jw = 0; jw < 8; jw++) {
        unsigned wd = smask[t * 8 + jw];
#pragma unroll
        for (int bit = 0; bit < 32; bit++) {
            float e = f1i + sf2[jw * 32 + bit];
            e = e > 0.0f ? e : ALPHA * e;
            if ((wd >> bit) & 1u) m = fmaxf(m, e);
        }
    }

    // ---- pass 2: exp/sum + weighted accumulate ----
    float sum = 0.0f;
    float acc[HH];
#pragma unroll
    for (int h = 0; h < HH; h++) acc[h] = 0.0f;

#pragma unroll 1
    for (int jw = 0; jw < 8; jw++) {
        unsigned wd = smask[t * 8 + jw];
#pragma unroll
        for (int bit = 0; bit < 32; bit++) {
            int j = jw * 32 + bit;
            float e = f1i + sf2[j];
            e = e > 0.0f ? e : ALPHA * e;
            float w = ((wd >> bit) & 1u) ? __expf(e - m) : 0.0f;
            sum += w;
#pragma unroll
            for (int h = 0; h < HH; h++) acc[h] += w * sWh[j * HH + h];
        }
    }

    float inv = 1.0f / sum;
    __half hv[16];
#pragma unroll
    for (int h = 0; h < HH; h++) hv[h] = __float2half_rn(acc[h] * inv);
    const uint4 u0 = *reinterpret_cast<uint4*>(hv);
    const uint4 u1 = *reinterpret_cast<uint4*>(hv + 8);

    // ---- scatter into tap-major B: k = tap*4096 + c, c in [t*16, t*16+16) ----
    int s = bs & 63;
    int c0 = t * HH;
    // own tap 1
    {
        uint4* p = reinterpret_cast<uint4*>(g_Bf + (size_t)bs * KTOT + 4096 + c0);
        p[0] = u0; p[1] = u1;
    }
    // tap 0 of col+1 (its s-1 sample = this s)
    if (s < 63) {
        uint4* p = reinterpret_cast<uint4*>(g_Bf + (size_t)(bs + 1) * KTOT + c0);
        p[0] = u0; p[1] = u1;
    }
    // tap 2 of col-1
    if (s > 0) {
        uint4* p = reinterpret_cast<uint4*>(g_Bf + (size_t)(bs - 1) * KTOT + 8192 + c0);
        p[0] = u0; p[1] = u1;
    }
    // boundary zero fills
    const uint4 z = make_uint4(0, 0, 0, 0);
    if (s == 0) {
        uint4* p = reinterpret_cast<uint4*>(g_Bf + (size_t)bs * KTOT + c0);
        p[0] = z; p[1] = z;
    }
    if (s == 63) {
        uint4* p = reinterpret_cast<uint4*>(g_Bf + (size_t)bs * KTOT + 8192 + c0);
        p[0] = z; p[1] = z;
    }
}

__device__ void cvt_body(int cb, const float* __restrict__ w) {
    // thread handles one (o, c0..c0+3): reads 12 consecutive fp32 (3 taps x 4 c),
    // writes 4 fp16 into each of the 3 tap planes (tap-major).
    int g = cb * 256 + threadIdx.x;        // 0 .. 4096*1024-1
    int o = g >> 10;
    int c0 = (g & 1023) * 4;
    const float* src = w + (size_t)o * KTOT + (size_t)c0 * 3;
    float4 v0 = *(const float4*)(src);
    float4 v1 = *(const float4*)(src + 4);
    float4 v2 = *(const float4*)(src + 8);
    float f[12] = {v0.x, v0.y, v0.z, v0.w, v1.x, v1.y, v1.z, v1.w,
                   v2.x, v2.y, v2.z, v2.w};
    __half hp[3][4];
#pragma unroll
    for (int i = 0; i < 4; i++) {
#pragma unroll
        for (int tap = 0; tap < 3; tap++)
            hp[tap][i] = __float2half_rn(f[i * 3 + tap]);
    }
    size_t base = (size_t)o * KTOT + c0;
#pragma unroll
    for (int tap = 0; tap < 3; tap++)
        *reinterpret_cast<uint2*>(g_Af + base + tap * 4096) =
            *reinterpret_cast<uint2*>(hp[tap]);
}

__global__ __launch_bounds__(256) void k_fat(const float* __restrict__ x,
                                             const float* __restrict__ W,
                                             const float* __restrict__ a1v,
                                             const float* __restrict__ a2v,
                                             const float* __restrict__ w) {
    if (blockIdx.x < GAT_BLOCKS)
        gat_body(blockIdx.x, x, W, a1v, a2v);
    else
        cvt_body(blockIdx.x - GAT_BLOCKS, w);
}

// ---------------------------------------------------------------------------
// Conv GEMM: fp16 HMMA. D[o][col] = A[o][:] . B[col][:]
// 128x128 CTA tile, BK=64, 3 stages, 8 warps (4M x 2N), warp tile m32n64.
// ---------------------------------------------------------------------------
__device__ __forceinline__ void issue_stage(unsigned sbs, int kb, int t,
                                            const __half* aG, const __half* bG) {
    int row = t >> 1;                   // 0..127
    int h2 = t & 1;
    unsigned rowB = (unsigned)(row * 128);
    unsigned swz = (unsigned)((row & 7) << 4);
    size_t go = (size_t)row * KTOT + kb;
#pragma unroll
    for (int j = 0; j < 4; j++) {
        int cidx = j * 2 + h2;
        unsigned dsw = rowB + (((unsigned)(cidx * 16)) ^ swz);
        size_t gs = go + cidx * 8;
        cp16(sbs + dsw,          aG + gs);
        cp16(sbs + 16384 + dsw,  bG + gs);
    }
    cp_commit();
}

__global__ __launch_bounds__(256, 1) void k_conv_mma() {
    extern __shared__ __align__(1024) char smem[];
    unsigned sb0 = (unsigned)__cvta_generic_to_shared(smem);

    int t = threadIdx.x;
    int wid = t >> 5;
    int L = t & 31;
    int wm = wid & 3;          // 4 warps along M (o)
    int wn = wid >> 2;         // 2 warps along N (col)
    int colBase = blockIdx.x * 128;
    int oBase = blockIdx.y * 128;

    const __half* aG = g_Af + (size_t)oBase * KTOT;
    const __half* bG = g_Bf + (size_t)colBase * KTOT;

    int l16 = L & 15;
    unsigned chB = (unsigned)(L >> 4);
    unsigned fSwz = (unsigned)((l16 & 7) << 4);
    unsigned aRow[2], bRow[4];
#pragma unroll
    for (int mt = 0; mt < 2; mt++) aRow[mt] = (unsigned)((wm * 32 + mt * 16 + l16) * 128);
#pragma unroll
    for (int q = 0; q < 4; q++) bRow[q] = (unsigned)((wn * 64 + q * 16 + l16) * 128);

    float d[2][8][4];
#pragma unroll
    for (int mt = 0; mt < 2; mt++)
#pragma unroll
        for (int nt = 0; nt < 8; nt++)
#pragma unroll
            for (int qq = 0; qq < 4; qq++) d[mt][nt][qq] = 0.0f;

    issue_stage(sb0, 0, t, aG, bG);
    issue_stage(sb0 + STAGEB, BK, t, aG, bG);

    for (int kt = 0; kt < NIT; kt++) {
        asm volatile("cp.async.wait_group 1;" ::: "memory");
        __syncthreads();

        if (kt + 2 < NIT)
            issue_stage(sb0 + (unsigned)((kt + 2) % 3) * STAGEB, (kt + 2) * BK,
                        t, aG, bG);
        else
            cp_commit();

        unsigned sb = sb0 + (unsigned)(kt % 3) * STAGEB;

#pragma unroll
        for (int ks = 0; ks < 4; ks++) {
            unsigned ch = ((unsigned)(ks * 2) + chB) << 4;
            unsigned chx = ch ^ fSwz;
            unsigned af[2][4], bf[4][4];
#pragma unroll
            for (int mt = 0; mt < 2; mt++)
                ldsm4(af[mt], sb + aRow[mt] + chx);
#pragma unroll
            for (int q = 0; q < 4; q++)
                ldsm4(bf[q], sb + 16384 + bRow[q] + chx);
#pragma unroll
            for (int mt = 0; mt < 2; mt++)
#pragma unroll
                for (int q = 0; q < 4; q++)
#pragma unroll
                    for (int h = 0; h < 2; h++) {
                        unsigned bv[2] = {bf[q][h], bf[q][h + 2]};
                        mma16816h(d[mt][q * 2 + h], af[mt], bv);
                    }
        }
    }

    int gid = L >> 2, tid4 = L & 3;
#pragma unroll
    for (int mt = 0; mt < 2; mt++) {
        int r = oBase + wm * 32 + mt * 16 + gid;
#pragma unroll
        for (int nt = 0; nt < 8; nt++) {
            int c = colBase + wn * 64 + nt * 8 + tid4 * 2;
            g_Yt[(size_t)c * CC + r]           = d[mt][nt][0];
            g_Yt[(size_t)(c + 1) * CC + r]     = d[mt][nt][1];
            g_Yt[(size_t)c * CC + r + 8]       = d[mt][nt][2];
            g_Yt[(size_t)(c + 1) * CC + r + 8] = d[mt][nt][3];
        }
    }
}

// ---------------------------------------------------------------------------
// Final: bias + BN + ReLU + residual + LayerNorm(H=16)
// ---------------------------------------------------------------------------
__global__ void k_final(const float* __restrict__ x,
                        const float* __restrict__ conv_b,
                        const float* __restrict__ bn_g, const float* __restrict__ bn_b,
                        const float* __restrict__ bn_m, const float* __restrict__ bn_v,
                        const float* __restrict__ ln_g, const float* __restrict__ ln_b,
                        float* __restrict__ out) {
    int bs = blockIdx.x, n = threadIdx.x;
    size_t base = (size_t)bs * CC + n * HH;
    size_t obase = (size_t)n * HH;

    float v[HH];
#pragma unroll
    for (int h = 0; h < HH; h += 4) {
        float4 y = *(const float4*)&g_Yt[base + h];
        float4 cb = *(const float4*)&conv_b[obase + h];
        float4 bm = *(const float4*)&bn_m[obase + h];
        float4 bvr = *(const float4*)&bn_v[obase + h];
        float4 bg = *(const float4*)&bn_g[obase + h];
        float4 bb = *(const float4*)&bn_b[obase + h];
        float4 xr = *(const float4*)&x[base + h];
        float yy[4] = {y.x, y.y, y.z, y.w};
        float cbv[4] = {cb.x, cb.y, cb.z, cb.w};
        float bmv[4] = {bm.x, bm.y, bm.z, bm.w};
        float bvv[4] = {bvr.x, bvr.y, bvr.z, bvr.w};
        float bgv[4] = {bg.x, bg.y, bg.z, bg.w};
        float bbv[4] = {bb.x, bb.y, bb.z, bb.w};
        float xv[4] = {xr.x, xr.y, xr.z, xr.w};
#pragma unroll
        for (int q = 0; q < 4; q++) {
            float val = yy[q] + cbv[q];
            val = (val - bmv[q]) * rsqrtf(bvv[q] + EPS) * bgv[q] + bbv[q];
            val = fmaxf(val, 0.0f);
            v[h + q] = val + xv[q];
        }
    }

    float mu = 0.0f;
#pragma unroll
    for (int h = 0; h < HH; h++) mu += v[h];
    mu *= (1.0f / HH);
    float var = 0.0f;
#pragma unroll
    for (int h = 0; h < HH; h++) { float dd = v[h] - mu; var += dd * dd; }
    var *= (1.0f / HH);
    float is = rsqrtf(var + EPS);

#pragma unroll
    for (int h = 0; h < HH; h++)
        out[base + h] = (v[h] - mu) * is * ln_g[h] + ln_b[h];
}

// ---------------------------------------------------------------------------
extern "C" void kernel_launch(void* const* d_in, const int* in_sizes, int n_in,
                              void* d_out, int out_size) {
    const float* x      = (const float*)d_in[0];
    const float* adj    = (const float*)d_in[1];
    const float* W      = (const float*)d_in[2];
    const float* a1     = (const float*)d_in[3];
    const float* a2     = (const float*)d_in[4];
    const float* conv_w = (const float*)d_in[5];
    const float* conv_b = (const float*)d_in[6];
    const float* bn_g   = (const float*)d_in[7];
    const float* bn_b   = (const float*)d_in[8];
    const float* bn_m   = (const float*)d_in[9];
    const float* bn_v   = (const float*)d_in[10];
    const float* ln_g   = (const float*)d_in[11];
    const float* ln_b   = (const float*)d_in[12];
    float* out = (float*)d_out;

    cudaFuncSetAttribute(k_conv_mma, cudaFuncAttributeMaxDynamicSharedMemorySize, SMEM_DYN);

    k_mask<<<8, 256>>>(adj);
    k_fat<<<GAT_BLOCKS + CVT_BLOCKS, 256>>>(x, W, a1, a2, conv_w);
    k_conv_mma<<<dim3(4, 32), 256, SMEM_DYN>>>();
    k_final<<<512, 256>>>(x, conv_b, bn_g, bn_b, bn_m, bn_v, ln_g, ln_b, out);
}

// round 10
// speedup vs baseline: 4.2895x; 1.0281x over previous
#include <cuda_runtime.h>
#include <cuda_fp16.h>
#include <cstdint>

// Problem constants
#define BB 8
#define SS 64
#define NN 256
#define FF 16
#define HH 16
#define CC 4096            // N*H  (= GEMM M)
#define COLS 512           // B*S  (= GEMM Ncol)
#define KTOT 12288         // C*3  (= GEMM K)
#define ALPHA 0.2f
#define EPS 1e-5f

// GEMM tiling (fp16 HMMA, single-term: D = A*B); K is tap-major: k = tap*4096 + c
#define BK 64                       // fp16 K per stage (128B rows)
#define TILEB 16384                 // 128 rows x 64 fp16 x 2B, xor-swizzled
#define STAGEB 32768                // A, B tiles
#define NSTAGE 3
#define NIT (KTOT / BK)             // 192
#define SMEM_DYN (NSTAGE * STAGEB)  // 98304 (also covers 128*132*4 epilogue tile)
#define LDSD 132                    // epilogue smem stride (floats)

#define GAT_BLOCKS 512
#define CVT_BLOCKS 16384            // 4096*1024 threads, 4 channels each

// ---------------- device scratch (no allocations allowed) -------------------
__device__ unsigned g_mask[NN * 8];
__device__ __half   g_Af[(size_t)CC * KTOT];       // fp16 weights (tap-major K)
__device__ __half   g_Bf[(size_t)COLS * KTOT];     // fp16 data (tap-major K)

// ---------------- PTX helpers ----------------------------------------------
__device__ __forceinline__ void cp16(unsigned dst, const void* src) {
    asm volatile("cp.async.cg.shared.global [%0], [%1], 16;" :: "r"(dst), "l"(src) : "memory");
}
__device__ __forceinline__ void cp_commit() {
    asm volatile("cp.async.commit_group;" ::: "memory");
}
__device__ __forceinline__ void ldsm4(unsigned* r, unsigned addr) {
    asm volatile("ldmatrix.sync.aligned.m8n8.x4.shared.b16 {%0,%1,%2,%3}, [%4];"
                 : "=r"(r[0]), "=r"(r[1]), "=r"(r[2]), "=r"(r[3]) : "r"(addr));
}
__device__ __forceinline__ void mma16816h(float* d, const unsigned* a, const unsigned* b) {
    asm volatile(
        "mma.sync.aligned.m16n8k16.row.col.f32.f16.f16.f32 "
        "{%0,%1,%2,%3}, {%4,%5,%6,%7}, {%8,%9}, {%0,%1,%2,%3};"
        : "+f"(d[0]), "+f"(d[1]), "+f"(d[2]), "+f"(d[3])
        : "r"(a[0]), "r"(a[1]), "r"(a[2]), "r"(a[3]), "r"(b[0]), "r"(b[1]));
}

// ---------------------------------------------------------------------------
// Kernel 0: adjacency bitmask
// ---------------------------------------------------------------------------
__global__ void k_mask(const float* __restrict__ adj) {
    int idx = blockIdx.x * blockDim.x + threadIdx.x;
    if (idx >= NN * 8) return;
    int i = idx >> 3, w = idx & 7;
    unsigned m = 0;
#pragma unroll
    for (int b = 0; b < 32; b++)
        if (adj[i * NN + w * 32 + b] > 0.0f) m |= (1u << b);
    g_mask[idx] = m;
}

// ---------------------------------------------------------------------------
// Fat kernel: blocks [0,512) = GAT (wh+attn+softmax+spatial+B scatter),
//             blocks [512, 512+16384) = weight convert fp32 -> fp16 tap-major.
// ---------------------------------------------------------------------------
__device__ void gat_body(int bs, const float* __restrict__ x,
                         const float* __restrict__ W,
                         const float* __restrict__ a1v,
                         const float* __restrict__ a2v) {
    __shared__ float    sW[FF * HH];
    __shared__ float    sa1[HH], sa2[HH];
    __shared__ float    sWh[NN * HH];
    __shared__ float    sf2[NN];
    __shared__ unsigned smask[NN * 8];

    int t = threadIdx.x;
    sW[t] = W[t];
    if (t < HH) { sa1[t] = a1v[t]; sa2[t] = a2v[t]; }
    for (int idx = t; idx < NN * 8; idx += 256) smask[idx] = g_mask[idx];
    __syncthreads();

    // ---- Wh = x @ W ; f1, f2 ----
    const float* xr = x + (size_t)(bs * NN + t) * FF;
    float xv[FF];
#pragma unroll
    for (int f = 0; f < FF; f += 4) {
        float4 v = *(const float4*)(xr + f);
        xv[f] = v.x; xv[f + 1] = v.y; xv[f + 2] = v.z; xv[f + 3] = v.w;
    }
    float wh[HH];
#pragma unroll
    for (int h = 0; h < HH; h++) wh[h] = 0.0f;
#pragma unroll
    for (int f = 0; f < FF; f++)
#pragma unroll
        for (int h = 0; h < HH; h++) wh[h] += xv[f] * sW[f * HH + h];

    float f1i = 0.0f, f2i = 0.0f;
#pragma unroll
    for (int h = 0; h < HH; h++) { f1i += wh[h] * sa1[h]; f2i += wh[h] * sa2[h]; }

#pragma unroll
    for (int h = 0; h < HH; h++) sWh[t * HH + h] = wh[h];
    sf2[t] = f2i;
    __syncthreads();

    // ---- masked softmax: pass 1 max ----
    float m = -1e30f;
#pragma unroll 1
    for (int jw = 0; jw < 8; jw++) {
        unsigned wd = smask[t * 8 + jw];
#pragma unroll
        for (int bit = 0; bit < 32; bit++) {
            float e = f1i + sf2[jw * 32 + bit];
            e = e > 0.0f ? e : ALPHA * e;
            if ((wd >> bit) & 1u) m = fmaxf(m, e);
        }
    }

    // ---- pass 2: exp/sum + weighted accumulate ----
    float sum = 0.0f;
    float acc[HH];
#pragma unroll
    for (int h = 0; h < HH; h++) acc[h] = 0.0f;

#pragma unroll 1
    for (int jw = 0; jw < 8; jw++) {
        unsigned wd = smask[t * 8 + jw];
#pragma unroll
        for (int bit = 0; bit < 32; bit++) {
            int j = jw * 32 + bit;
            float e = f1i + sf2[j];
            e = e > 0.0f ? e : ALPHA * e;
            float w = ((wd >> bit) & 1u) ? __expf(e - m) : 0.0f;
            sum += w;
#pragma unroll
            for (int h = 0; h < HH; h++) acc[h] += w * sWh[j * HH + h];
        }
    }

    float inv = 1.0f / sum;
    __half hv[16];
#pragma unroll
    for (int h = 0; h < HH; h++) hv[h] = __float2half_rn(acc[h] * inv);
    const uint4 u0 = *reinterpret_cast<uint4*>(hv);
    const uint4 u1 = *reinterpret_cast<uint4*>(hv + 8);

    // ---- scatter into tap-major B: k = tap*4096 + c, c in [t*16, t*16+16) ----
    int s = bs & 63;
    int c0 = t * HH;
    {   // own tap 1
        uint4* p = reinterpret_cast<uint4*>(g_Bf + (size_t)bs * KTOT + 4096 + c0);
        p[0] = u0; p[1] = u1;
    }
    if (s < 63) {   // tap 0 of col+1
        uint4* p = reinterpret_cast<uint4*>(g_Bf + (size_t)(bs + 1) * KTOT + c0);
        p[0] = u0; p[1] = u1;
    }
    if (s > 0) {    // tap 2 of col-1
        uint4* p = reinterpret_cast<uint4*>(g_Bf + (size_t)(bs - 1) * KTOT + 8192 + c0);
        p[0] = u0; p[1] = u1;
    }
    const uint4 z = make_uint4(0, 0, 0, 0);
    if (s == 0) {
        uint4* p = reinterpret_cast<uint4*>(g_Bf + (size_t)bs * KTOT + c0);
        p[0] = z; p[1] = z;
    }
    if (s == 63) {
        uint4* p = reinterpret_cast<uint4*>(g_Bf + (size_t)bs * KTOT + 8192 + c0);
        p[0] = z; p[1] = z;
    }
}

__device__ void cvt_body(int cb, const float* __restrict__ w) {
    int g = cb * 256 + threadIdx.x;        // 0 .. 4096*1024-1
    int o = g >> 10;
    int c0 = (g & 1023) * 4;
    const float* src = w + (size_t)o * KTOT + (size_t)c0 * 3;
    float4 v0 = *(const float4*)(src);
    float4 v1 = *(const float4*)(src + 4);
    float4 v2 = *(const float4*)(src + 8);
    float f[12] = {v0.x, v0.y, v0.z, v0.w, v1.x, v1.y, v1.z, v1.w,
                   v2.x, v2.y, v2.z, v2.w};
    __half hp[3][4];
#pragma unroll
    for (int i = 0; i < 4; i++) {
#pragma unroll
        for (int tap = 0; tap < 3; tap++)
            hp[tap][i] = __float2half_rn(f[i * 3 + tap]);
    }
    size_t base = (size_t)o * KTOT + c0;
#pragma unroll
    for (int tap = 0; tap < 3; tap++)
        *reinterpret_cast<uint2*>(g_Af + base + tap * 4096) =
            *reinterpret_cast<uint2*>(hp[tap]);
}

__global__ __launch_bounds__(256) void k_fat(const float* __restrict__ x,
                                             const float* __restrict__ W,
                                             const float* __restrict__ a1v,
                                             const float* __restrict__ a2v,
                                             const float* __restrict__ w) {
    if (blockIdx.x < GAT_BLOCKS)
        gat_body(blockIdx.x, x, W, a1v, a2v);
    else
        cvt_body(blockIdx.x - GAT_BLOCKS, w);
}

// ---------------------------------------------------------------------------
// Conv GEMM + fused epilogue. D[o][col] = A[o][:].B[col][:], then
// bias+BN+ReLU+residual+LayerNorm straight to out.
// 128x128 CTA tile, BK=64, 3 stages, 8 warps (4M x 2N), warp tile m32n64.
// ---------------------------------------------------------------------------
__device__ __forceinline__ void issue_stage(unsigned sbs, int kb, int t,
                                            const __half* aG, const __half* bG) {
    int row = t >> 1;                   // 0..127
    int h2 = t & 1;
    unsigned rowB = (unsigned)(row * 128);
    unsigned swz = (unsigned)((row & 7) << 4);
    size_t go = (size_t)row * KTOT + kb;
#pragma unroll
    for (int j = 0; j < 4; j++) {
        int cidx = j * 2 + h2;
        unsigned dsw = rowB + (((unsigned)(cidx * 16)) ^ swz);
        size_t gs = go + cidx * 8;
        cp16(sbs + dsw,          aG + gs);
        cp16(sbs + 16384 + dsw,  bG + gs);
    }
    cp_commit();
}

__global__ __launch_bounds__(256, 1) void k_conv_mma(
        const float* __restrict__ x,
        const float* __restrict__ conv_b,
        const float* __restrict__ bn_g, const float* __restrict__ bn_b,
        const float* __restrict__ bn_m, const float* __restrict__ bn_v,
        const float* __restrict__ ln_g, const float* __restrict__ ln_b,
        float* __restrict__ out) {
    extern __shared__ __align__(1024) char smem[];
    unsigned sb0 = (unsigned)__cvta_generic_to_shared(smem);

    int t = threadIdx.x;
    int wid = t >> 5;
    int L = t & 31;
    int wm = wid & 3;          // 4 warps along M (o)
    int wn = wid >> 2;         // 2 warps along N (col)
    int colBase = blockIdx.x * 128;
    int oBase = blockIdx.y * 128;

    const __half* aG = g_Af + (size_t)oBase * KTOT;
    const __half* bG = g_Bf + (size_t)colBase * KTOT;

    int l16 = L & 15;
    unsigned chB = (unsigned)(L >> 4);
    unsigned fSwz = (unsigned)((l16 & 7) << 4);
    unsigned aRow[2], bRow[4];
#pragma unroll
    for (int mt = 0; mt < 2; mt++) aRow[mt] = (unsigned)((wm * 32 + mt * 16 + l16) * 128);
#pragma unroll
    for (int q = 0; q < 4; q++) bRow[q] = (unsigned)((wn * 64 + q * 16 + l16) * 128);

    float d[2][8][4];
#pragma unroll
    for (int mt = 0; mt < 2; mt++)
#pragma unroll
        for (int nt = 0; nt < 8; nt++)
#pragma unroll
            for (int qq = 0; qq < 4; qq++) d[mt][nt][qq] = 0.0f;

    issue_stage(sb0, 0, t, aG, bG);
    issue_stage(sb0 + STAGEB, BK, t, aG, bG);

    for (int kt = 0; kt < NIT; kt++) {
        asm volatile("cp.async.wait_group 1;" ::: "memory");
        __syncthreads();

        if (kt + 2 < NIT)
            issue_stage(sb0 + (unsigned)((kt + 2) % 3) * STAGEB, (kt + 2) * BK,
                        t, aG, bG);
        else
            cp_commit();

        unsigned sb = sb0 + (unsigned)(kt % 3) * STAGEB;

#pragma unroll
        for (int ks = 0; ks < 4; ks++) {
            unsigned ch = ((unsigned)(ks * 2) + chB) << 4;
            unsigned chx = ch ^ fSwz;
            unsigned af[2][4], bf[4][4];
#pragma unroll
            for (int mt = 0; mt < 2; mt++)
                ldsm4(af[mt], sb + aRow[mt] + chx);
#pragma unroll
            for (int q = 0; q < 4; q++)
                ldsm4(bf[q], sb + 16384 + bRow[q] + chx);
#pragma unroll
            for (int mt = 0; mt < 2; mt++)
#pragma unroll
                for (int q = 0; q < 4; q++)
#pragma unroll
                    for (int h = 0; h < 2; h++) {
                        unsigned bv[2] = {bf[q][h], bf[q][h + 2]};
                        mma16816h(d[mt][q * 2 + h], af[mt], bv);
                    }
        }
    }

    // ---- fused epilogue: stage tile to smem as [col][o], then LN to out ----
    asm volatile("cp.async.wait_group 0;" ::: "memory");
    __syncthreads();                  // all warps done with pipeline smem
    float* sD = reinterpret_cast<float*>(smem);

    int gid = L >> 2, tid4 = L & 3;
#pragma unroll
    for (int mt = 0; mt < 2; mt++) {
        int rl = wm * 32 + mt * 16 + gid;
#pragma unroll
        for (int nt = 0; nt < 8; nt++) {
            int cl = wn * 64 + nt * 8 + tid4 * 2;
            sD[cl * LDSD + rl]             = d[mt][nt][0];
            sD[(cl + 1) * LDSD + rl]       = d[mt][nt][1];
            sD[cl * LDSD + rl + 8]         = d[mt][nt][2];
            sD[(cl + 1) * LDSD + rl + 8]   = d[mt][nt][3];
        }
    }
    __syncthreads();

    // ln params for this CTA's h range (h = 0..15 always)
#pragma unroll 1
    for (int it = 0; it < 4; it++) {
        int task = t + it * 256;          // 0..1023
        int cl = task & 127;
        int ng = task >> 7;               // 0..7
        int o0 = oBase + ng * 16;         // global channel base (= n*16)
        int colg = colBase + cl;
        size_t gbase = (size_t)colg * CC + o0;

        float v[HH];
#pragma unroll
        for (int h = 0; h < HH; h += 4) {
            float4 y = *(const float4*)&sD[cl * LDSD + ng * 16 + h];
            float4 cb = *(const float4*)&conv_b[o0 + h];
            float4 bm = *(const float4*)&bn_m[o0 + h];
            float4 bvr = *(const float4*)&bn_v[o0 + h];
            float4 bg = *(const float4*)&bn_g[o0 + h];
            float4 bb = *(const float4*)&bn_b[o0 + h];
            float4 xr = *(const float4*)&x[gbase + h];
            float yy[4] = {y.x, y.y, y.z, y.w};
            float cbv[4] = {cb.x, cb.y, cb.z, cb.w};
            float bmv[4] = {bm.x, bm.y, bm.z, bm.w};
            float bvv[4] = {bvr.x, bvr.y, bvr.z, bvr.w};
            float bgv[4] = {bg.x, bg.y, bg.z, bg.w};
            float bbv[4] = {bb.x, bb.y, bb.z, bb.w};
            float xv[4] = {xr.x, xr.y, xr.z, xr.w};
#pragma unroll
            for (int q = 0; q < 4; q++) {
                float val = yy[q] + cbv[q];
                val = (val - bmv[q]) * rsqrtf(bvv[q] + EPS) * bgv[q] + bbv[q];
                val = fmaxf(val, 0.0f);
                v[h + q] = val + xv[q];
            }
        }

        float mu = 0.0f;
#pragma unroll
        for (int h = 0; h < HH; h++) mu += v[h];
        mu *= (1.0f / HH);
        float var = 0.0f;
#pragma unroll
        for (int h = 0; h < HH; h++) { float dd = v[h] - mu; var += dd * dd; }
        var *= (1.0f / HH);
        float is = rsqrtf(var + EPS);

#pragma unroll
        for (int h = 0; h < HH; h += 4) {
            float4 lg = *(const float4*)&ln_g[h];
            float4 lb = *(const float4*)&ln_b[h];
            float4 o;
            o.x = (v[h]     - mu) * is * lg.x + lb.x;
            o.y = (v[h + 1] - mu) * is * lg.y + lb.y;
            o.z = (v[h + 2] - mu) * is * lg.z + lb.z;
            o.w = (v[h + 3] - mu) * is * lg.w + lb.w;
            *(float4*)&out[gbase + h] = o;
        }
    }
}

// ---------------------------------------------------------------------------
extern "C" void kernel_launch(void* const* d_in, const int* in_sizes, int n_in,
                              void* d_out, int out_size) {
    const float* x      = (const float*)d_in[0];
    const float* adj    = (const float*)d_in[1];
    const float* W      = (const float*)d_in[2];
    const float* a1     = (const float*)d_in[3];
    const float* a2     = (const float*)d_in[4];
    const float* conv_w = (const float*)d_in[5];
    const float* conv_b = (const float*)d_in[6];
    const float* bn_g   = (const float*)d_in[7];
    const float* bn_b   = (const float*)d_in[8];
    const float* bn_m   = (const float*)d_in[9];
    const float* bn_v   = (const float*)d_in[10];
    const float* ln_g   = (const float*)d_in[11];
    const float* ln_b   = (const float*)d_in[12];
    float* out = (float*)d_out;

    cudaFuncSetAttribute(k_conv_mma, cudaFuncAttributeMaxDynamicSharedMemorySize, SMEM_DYN);

    k_mask<<<8, 256>>>(adj);
    k_fat<<<GAT_BLOCKS + CVT_BLOCKS, 256>>>(x, W, a1, a2, conv_w);
    k_conv_mma<<<dim3(4, 32), 256, SMEM_DYN>>>(x, conv_b, bn_g, bn_b,
                                               bn_m, bn_v, ln_g, ln_b, out);
}

// round 11
// speedup vs baseline: 4.4308x; 1.0329x over previous
#include <cuda_runtime.h>
#include <cuda_fp16.h>
#include <cstdint>

// Problem constants
#define BB 8
#define SS 64
#define NN 256
#define FF 16
#define HH 16
#define CC 4096            // N*H  (= GEMM M)
#define COLS 512           // B*S  (= GEMM Ncol)
#define KTOT 12288         // C*3  (= GEMM K)
#define ALPHA 0.2f
#define EPS 1e-5f

// GEMM tiling (fp16 HMMA, single-term: D = A*B); K is tap-major: k = tap*4096 + c
#define BK 64                       // fp16 K per stage (128B rows)
#define TILEB 16384                 // 128 rows x 64 fp16 x 2B, xor-swizzled
#define STAGEB 32768                // A, B tiles
#define NSTAGE 4
#define NIT (KTOT / BK)             // 192
#define SMEM_DYN (NSTAGE * STAGEB)  // 131072 (also covers 128*132*4 epilogue tile)
#define LDSD 132                    // epilogue smem stride (floats)

#define GAT_BLOCKS 512
#define CVT_BLOCKS 16384            // 4096*1024 threads, 4 channels each

// ---------------- device scratch (no allocations allowed) -------------------
__device__ unsigned g_mask[NN * 8];
__device__ __half   g_Af[(size_t)CC * KTOT];       // fp16 weights (tap-major K)
__device__ __half   g_Bf[(size_t)COLS * KTOT];     // fp16 data (tap-major K)

// ---------------- PTX helpers ----------------------------------------------
__device__ __forceinline__ void cp16(unsigned dst, const void* src) {
    asm volatile("cp.async.cg.shared.global [%0], [%1], 16;" :: "r"(dst), "l"(src) : "memory");
}
__device__ __forceinline__ void cp_commit() {
    asm volatile("cp.async.commit_group;" ::: "memory");
}
__device__ __forceinline__ void ldsm4(unsigned* r, unsigned addr) {
    asm volatile("ldmatrix.sync.aligned.m8n8.x4.shared.b16 {%0,%1,%2,%3}, [%4];"
                 : "=r"(r[0]), "=r"(r[1]), "=r"(r[2]), "=r"(r[3]) : "r"(addr));
}
__device__ __forceinline__ void mma16816h(float* d, const unsigned* a, const unsigned* b) {
    asm volatile(
        "mma.sync.aligned.m16n8k16.row.col.f32.f16.f16.f32 "
        "{%0,%1,%2,%3}, {%4,%5,%6,%7}, {%8,%9}, {%0,%1,%2,%3};"
        : "+f"(d[0]), "+f"(d[1]), "+f"(d[2]), "+f"(d[3])
        : "r"(a[0]), "r"(a[1]), "r"(a[2]), "r"(a[3]), "r"(b[0]), "r"(b[1]));
}

// ---------------------------------------------------------------------------
// Kernel 0: adjacency bitmask, one ballot per word (2048 warps)
// ---------------------------------------------------------------------------
__global__ void k_mask(const float* __restrict__ adj) {
    int gw = (blockIdx.x * 256 + threadIdx.x) >> 5;   // global warp 0..2047
    int lane = threadIdx.x & 31;
    int i = gw >> 3, w = gw & 7;
    float v = adj[i * NN + w * 32 + lane];
    unsigned m = __ballot_sync(0xffffffffu, v > 0.0f);
    if (lane == 0) g_mask[gw] = m;
}

// ---------------------------------------------------------------------------
// Fat kernel: blocks [0,512) = GAT (wh+attn+softmax+spatial+B scatter),
//             blocks [512, 512+16384) = weight convert fp32 -> fp16 tap-major.
// ---------------------------------------------------------------------------
__device__ void gat_body(int bs, const float* __restrict__ x,
                         const float* __restrict__ W,
                         const float* __restrict__ a1v,
                         const float* __restrict__ a2v) {
    __shared__ float    sW[FF * HH];
    __shared__ float    sa1[HH], sa2[HH];
    __shared__ float    sWh[NN * HH];
    __shared__ float    sf2[NN];
    __shared__ unsigned smask[NN * 8];

    int t = threadIdx.x;
    sW[t] = W[t];
    if (t < HH) { sa1[t] = a1v[t]; sa2[t] = a2v[t]; }
    for (int idx = t; idx < NN * 8; idx += 256) smask[idx] = g_mask[idx];
    __syncthreads();

    // ---- Wh = x @ W ; f1, f2 ----
    const float* xr = x + (size_t)(bs * NN + t) * FF;
    float xv[FF];
#pragma unroll
    for (int f = 0; f < FF; f += 4) {
        float4 v = *(const float4*)(xr + f);
        xv[f] = v.x; xv[f + 1] = v.y; xv[f + 2] = v.z; xv[f + 3] = v.w;
    }
    float wh[HH];
#pragma unroll
    for (int h = 0; h < HH; h++) wh[h] = 0.0f;
#pragma unroll
    for (int f = 0; f < FF; f++)
#pragma unroll
        for (int h = 0; h < HH; h++) wh[h] += xv[f] * sW[f * HH + h];

    float f1i = 0.0f, f2i = 0.0f;
#pragma unroll
    for (int h = 0; h < HH; h++) { f1i += wh[h] * sa1[h]; f2i += wh[h] * sa2[h]; }

#pragma unroll
    for (int h = 0; h < HH; h++) sWh[t * HH + h] = wh[h];
    sf2[t] = f2i;
    __syncthreads();

    // ---- masked softmax: pass 1 max ----
    float m = -1e30f;
#pragma unroll 1
    for (int jw = 0; jw < 8; jw++) {
        unsigned wd = smask[t * 8 + jw];
#pragma unroll
        for (int bit = 0; bit < 32; bit++) {
            float e = f1i + sf2[jw * 32 + bit];
            e = e > 0.0f ? e : ALPHA * e;
            if ((wd >> bit) & 1u) m = fmaxf(m, e);
        }
    }

    // ---- pass 2: exp/sum + weighted accumulate ----
    float sum = 0.0f;
    float acc[HH];
#pragma unroll
    for (int h = 0; h < HH; h++) acc[h] = 0.0f;

#pragma unroll 1
    for (int jw = 0; jw < 8; jw++) {
        unsigned wd = smask[t * 8 + jw];
#pragma unroll
        for (int bit = 0; bit < 32; bit++) {
            int j = jw * 32 + bit;
            float e = f1i + sf2[j];
            e = e > 0.0f ? e : ALPHA * e;
            float w = ((wd >> bit) & 1u) ? __expf(e - m) : 0.0f;
            sum += w;
#pragma unroll
            for (int h = 0; h < HH; h++) acc[h] += w * sWh[j * HH + h];
        }
    }

    float inv = 1.0f / sum;
    __half hv[16];
#pragma unroll
    for (int h = 0; h < HH; h++) hv[h] = __float2half_rn(acc[h] * inv);
    const uint4 u0 = *reinterpret_cast<uint4*>(hv);
    const uint4 u1 = *reinterpret_cast<uint4*>(hv + 8);

    // ---- scatter into tap-major B: k = tap*4096 + c, c in [t*16, t*16+16) ----
    int s = bs & 63;
    int c0 = t * HH;
    {   // own tap 1
        uint4* p = reinterpret_cast<uint4*>(g_Bf + (size_t)bs * KTOT + 4096 + c0);
        p[0] = u0; p[1] = u1;
    }
    if (s < 63) {   // tap 0 of col+1
        uint4* p = reinterpret_cast<uint4*>(g_Bf + (size_t)(bs + 1) * KTOT + c0);
        p[0] = u0; p[1] = u1;
    }
    if (s > 0) {    // tap 2 of col-1
        uint4* p = reinterpret_cast<uint4*>(g_Bf + (size_t)(bs - 1) * KTOT + 8192 + c0);
        p[0] = u0; p[1] = u1;
    }
    const uint4 z = make_uint4(0, 0, 0, 0);
    if (s == 0) {
        uint4* p = reinterpret_cast<uint4*>(g_Bf + (size_t)bs * KTOT + c0);
        p[0] = z; p[1] = z;
    }
    if (s == 63) {
        uint4* p = reinterpret_cast<uint4*>(g_Bf + (size_t)bs * KTOT + 8192 + c0);
        p[0] = z; p[1] = z;
    }
}

__device__ void cvt_body(int cb, const float* __restrict__ w) {
    int g = cb * 256 + threadIdx.x;        // 0 .. 4096*1024-1
    int o = g >> 10;
    int c0 = (g & 1023) * 4;
    const float* src = w + (size_t)o * KTOT + (size_t)c0 * 3;
    float4 v0 = *(const float4*)(src);
    float4 v1 = *(const float4*)(src + 4);
    float4 v2 = *(const float4*)(src + 8);
    float f[12] = {v0.x, v0.y, v0.z, v0.w, v1.x, v1.y, v1.z, v1.w,
                   v2.x, v2.y, v2.z, v2.w};
    __half hp[3][4];
#pragma unroll
    for (int i = 0; i < 4; i++) {
#pragma unroll
        for (int tap = 0; tap < 3; tap++)
            hp[tap][i] = __float2half_rn(f[i * 3 + tap]);
    }
    size_t base = (size_t)o * KTOT + c0;
#pragma unroll
    for (int tap = 0; tap < 3; tap++)
        *reinterpret_cast<uint2*>(g_Af + base + tap * 4096) =
            *reinterpret_cast<uint2*>(hp[tap]);
}

__global__ __launch_bounds__(256) void k_fat(const float* __restrict__ x,
                                             const float* __restrict__ W,
                                             const float* __restrict__ a1v,
                                             const float* __restrict__ a2v,
                                             const float* __restrict__ w) {
    if (blockIdx.x < GAT_BLOCKS)
        gat_body(blockIdx.x, x, W, a1v, a2v);
    else
        cvt_body(blockIdx.x - GAT_BLOCKS, w);
}

// ---------------------------------------------------------------------------
// Conv GEMM + fused epilogue. D[o][col] = A[o][:].B[col][:], then
// bias+BN+ReLU+residual+LayerNorm straight to out.
// 128x128 CTA tile, BK=64, 4 stages, 8 warps (4M x 2N), warp tile m32n64.
// ---------------------------------------------------------------------------
__device__ __forceinline__ void issue_stage(unsigned sbs, int kb, int t,
                                            const __half* aG, const __half* bG) {
    int row = t >> 1;                   // 0..127
    int h2 = t & 1;
    unsigned rowB = (unsigned)(row * 128);
    unsigned swz = (unsigned)((row & 7) << 4);
    size_t go = (size_t)row * KTOT + kb;
#pragma unroll
    for (int j = 0; j < 4; j++) {
        int cidx = j * 2 + h2;
        unsigned dsw = rowB + (((unsigned)(cidx * 16)) ^ swz);
        size_t gs = go + cidx * 8;
        cp16(sbs + dsw,          aG + gs);
        cp16(sbs + 16384 + dsw,  bG + gs);
    }
    cp_commit();
}

__global__ __launch_bounds__(256, 1) void k_conv_mma(
        const float* __restrict__ x,
        const float* __restrict__ conv_b,
        const float* __restrict__ bn_g, const float* __restrict__ bn_b,
        const float* __restrict__ bn_m, const float* __restrict__ bn_v,
        const float* __restrict__ ln_g, const float* __restrict__ ln_b,
        float* __restrict__ out) {
    extern __shared__ __align__(1024) char smem[];
    unsigned sb0 = (unsigned)__cvta_generic_to_shared(smem);

    int t = threadIdx.x;
    int wid = t >> 5;
    int L = t & 31;
    int wm = wid & 3;          // 4 warps along M (o)
    int wn = wid >> 2;         // 2 warps along N (col)
    int colBase = blockIdx.x * 128;
    int oBase = blockIdx.y * 128;

    const __half* aG = g_Af + (size_t)oBase * KTOT;
    const __half* bG = g_Bf + (size_t)colBase * KTOT;

    int l16 = L & 15;
    unsigned chB = (unsigned)(L >> 4);
    unsigned fSwz = (unsigned)((l16 & 7) << 4);
    unsigned aRow[2], bRow[4];
#pragma unroll
    for (int mt = 0; mt < 2; mt++) aRow[mt] = (unsigned)((wm * 32 + mt * 16 + l16) * 128);
#pragma unroll
    for (int q = 0; q < 4; q++) bRow[q] = (unsigned)((wn * 64 + q * 16 + l16) * 128);

    float d[2][8][4];
#pragma unroll
    for (int mt = 0; mt < 2; mt++)
#pragma unroll
        for (int nt = 0; nt < 8; nt++)
#pragma unroll
            for (int qq = 0; qq < 4; qq++) d[mt][nt][qq] = 0.0f;

    issue_stage(sb0, 0, t, aG, bG);
    issue_stage(sb0 + STAGEB, BK, t, aG, bG);
    issue_stage(sb0 + 2 * STAGEB, 2 * BK, t, aG, bG);

    for (int kt = 0; kt < NIT; kt++) {
        asm volatile("cp.async.wait_group 2;" ::: "memory");
        __syncthreads();

        if (kt + 3 < NIT)
            issue_stage(sb0 + (unsigned)((kt + 3) & 3) * STAGEB, (kt + 3) * BK,
                        t, aG, bG);
        else
            cp_commit();

        unsigned sb = sb0 + (unsigned)(kt & 3) * STAGEB;

#pragma unroll
        for (int ks = 0; ks < 4; ks++) {
            unsigned ch = ((unsigned)(ks * 2) + chB) << 4;
            unsigned chx = ch ^ fSwz;
            unsigned af[2][4], bf[4][4];
#pragma unroll
            for (int mt = 0; mt < 2; mt++)
                ldsm4(af[mt], sb + aRow[mt] + chx);
#pragma unroll
            for (int q = 0; q < 4; q++)
                ldsm4(bf[q], sb + 16384 + bRow[q] + chx);
#pragma unroll
            for (int mt = 0; mt < 2; mt++)
#pragma unroll
                for (int q = 0; q < 4; q++)
#pragma unroll
                    for (int h = 0; h < 2; h++) {
                        unsigned bv[2] = {bf[q][h], bf[q][h + 2]};
                        mma16816h(d[mt][q * 2 + h], af[mt], bv);
                    }
        }
    }

    // ---- fused epilogue: stage tile to smem as [col][o], then LN to out ----
    asm volatile("cp.async.wait_group 0;" ::: "memory");
    __syncthreads();                  // all warps done with pipeline smem
    float* sD = reinterpret_cast<float*>(smem);

    int gid = L >> 2, tid4 = L & 3;
#pragma unroll
    for (int mt = 0; mt < 2; mt++) {
        int rl = wm * 32 + mt * 16 + gid;
#pragma unroll
        for (int nt = 0; nt < 8; nt++) {
            int cl = wn * 64 + nt * 8 + tid4 * 2;
            sD[cl * LDSD + rl]             = d[mt][nt][0];
            sD[(cl + 1) * LDSD + rl]       = d[mt][nt][1];
            sD[cl * LDSD + rl + 8]         = d[mt][nt][2];
            sD[(cl + 1) * LDSD + rl + 8]   = d[mt][nt][3];
        }
    }
    __syncthreads();

    float lg[HH], lb[HH];
#pragma unroll
    for (int h = 0; h < HH; h += 4) {
        float4 g4 = *(const float4*)&ln_g[h];
        float4 b4 = *(const float4*)&ln_b[h];
        lg[h] = g4.x; lg[h + 1] = g4.y; lg[h + 2] = g4.z; lg[h + 3] = g4.w;
        lb[h] = b4.x; lb[h + 1] = b4.y; lb[h + 2] = b4.z; lb[h + 3] = b4.w;
    }

    // task = cl*8 + ng so consecutive threads cover consecutive channel groups
#pragma unroll 1
    for (int it = 0; it < 4; it++) {
        int task = t + it * 256;          // 0..1023
        int ng = task & 7;                // 0..7
        int cl = task >> 3;               // 0..127
        int o0 = oBase + ng * 16;         // global channel base (= n*16)
        int colg = colBase + cl;
        size_t gbase = (size_t)colg * CC + o0;

        float v[HH];
#pragma unroll
        for (int h = 0; h < HH; h += 4) {
            float4 y = *(const float4*)&sD[cl * LDSD + ng * 16 + h];
            float4 cb = *(const float4*)&conv_b[o0 + h];
            float4 bm = *(const float4*)&bn_m[o0 + h];
            float4 bvr = *(const float4*)&bn_v[o0 + h];
            float4 bg = *(const float4*)&bn_g[o0 + h];
            float4 bb = *(const float4*)&bn_b[o0 + h];
            float4 xr = *(const float4*)&x[gbase + h];
            float yy[4] = {y.x, y.y, y.z, y.w};
            float cbv[4] = {cb.x, cb.y, cb.z, cb.w};
            float bmv[4] = {bm.x, bm.y, bm.z, bm.w};
            float bvv[4] = {bvr.x, bvr.y, bvr.z, bvr.w};
            float bgv[4] = {bg.x, bg.y, bg.z, bg.w};
            float bbv[4] = {bb.x, bb.y, bb.z, bb.w};
            float xv[4] = {xr.x, xr.y, xr.z, xr.w};
#pragma unroll
            for (int q = 0; q < 4; q++) {
                float val = yy[q] + cbv[q];
                val = (val - bmv[q]) * rsqrtf(bvv[q] + EPS) * bgv[q] + bbv[q];
                val = fmaxf(val, 0.0f);
                v[h + q] = val + xv[q];
            }
        }

        float mu = 0.0f;
#pragma unroll
        for (int h = 0; h < HH; h++) mu += v[h];
        mu *= (1.0f / HH);
        float var = 0.0f;
#pragma unroll
        for (int h = 0; h < HH; h++) { float dd = v[h] - mu; var += dd * dd; }
        var *= (1.0f / HH);
        float is = rsqrtf(var + EPS);

#pragma unroll
        for (int h = 0; h < HH; h += 4) {
            float4 o;
            o.x = (v[h]     - mu) * is * lg[h]     + lb[h];
            o.y = (v[h + 1] - mu) * is * lg[h + 1] + lb[h + 1];
            o.z = (v[h + 2] - mu) * is * lg[h + 2] + lb[h + 2];
            o.w = (v[h + 3] - mu) * is * lg[h + 3] + lb[h + 3];
            *(float4*)&out[gbase + h] = o;
        }
    }
}

// ---------------------------------------------------------------------------
extern "C" void kernel_launch(void* const* d_in, const int* in_sizes, int n_in,
                              void* d_out, int out_size) {
    const float* x      = (const float*)d_in[0];
    const float* adj    = (const float*)d_in[1];
    const float* W      = (const float*)d_in[2];
    const float* a1     = (const float*)d_in[3];
    const float* a2     = (const float*)d_in[4];
    const float* conv_w = (const float*)d_in[5];
    const float* conv_b = (const float*)d_in[6];
    const float* bn_g   = (const float*)d_in[7];
    const float* bn_b   = (const float*)d_in[8];
    const float* bn_m   = (const float*)d_in[9];
    const float* bn_v   = (const float*)d_in[10];
    const float* ln_g   = (const float*)d_in[11];
    const float* ln_b   = (const float*)d_in[12];
    float* out = (float*)d_out;

    cudaFuncSetAttribute(k_conv_mma, cudaFuncAttributeMaxDynamicSharedMemorySize, SMEM_DYN);

    k_mask<<<256, 256>>>(adj);
    k_fat<<<GAT_BLOCKS + CVT_BLOCKS, 256>>>(x, W, a1, a2, conv_w);
    k_conv_mma<<<dim3(4, 32), 256, SMEM_DYN>>>(x, conv_b, bn_g, bn_b,
                                               bn_m, bn_v, ln_g, ln_b, out);
}